// round 1
// baseline (speedup 1.0000x reference)
#include <cuda_runtime.h>
#include <cuda_bf16.h>
#include <math.h>

// Problem dims
#define NB   256      // graphs (B)
#define NPG  64       // nodes per graph
#define DEG  8
#define NN   (NB*NPG)         // 16384 nodes
#define NE   (NN*DEG)         // 131072 edges
#define NODE_IN 64
#define EDGE_IN 32
#define HD   256      // H
#define NL   4        // GAT layers
#define HEADS 8
#define DK   32       // H/HEADS
#define FF   512      // 2*H

// ---------------- scratch (device globals; no allocation allowed) ----------
__device__ float d_h[NN*HD];       // node state
__device__ float d_m[NN*HD];       // per-layer transformed features / gate relu
__device__ float d_s1[NN];
__device__ float d_s2[NN];
__device__ float d_s3[NE];
__device__ float d_w3c[64];        // We@a3 (32) + c3 at [32]
__device__ float d_q[NN*HD];
__device__ float d_k[NN*HD];
__device__ float d_v[NN*HD];
__device__ float d_tmp[NN*HD];     // attention out / ff out
__device__ float d_ff[NN*FF];
__device__ float d_g[NN];

// ---------------- generic tiled GEMM: C = act(A[M,K] @ B[K,Nc] + bias) -----
// act: 0=none, 1=relu, 2=gelu(exact)
__global__ void gemm_kernel(const float* __restrict__ A, const float* __restrict__ B,
                            const float* __restrict__ bias, float* __restrict__ C,
                            int M, int Nc, int K, int act) {
    __shared__ float As[32][33];
    __shared__ float Bs[32][33];
    int tx = threadIdx.x, ty = threadIdx.y;
    int row = blockIdx.y * 32 + ty;
    int col = blockIdx.x * 32 + tx;
    float acc = 0.0f;
    for (int k0 = 0; k0 < K; k0 += 32) {
        As[ty][tx] = A[row * K + (k0 + tx)];
        Bs[ty][tx] = B[(k0 + ty) * Nc + col];
        __syncthreads();
        #pragma unroll
        for (int kk = 0; kk < 32; kk++)
            acc = fmaf(As[ty][kk], Bs[kk][tx], acc);
        __syncthreads();
    }
    float v = acc + (bias ? bias[col] : 0.0f);
    if (act == 1) v = fmaxf(v, 0.0f);
    else if (act == 2) v = 0.5f * v * (1.0f + erff(v * 0.70710678118654752f));
    C[row * Nc + col] = v;
}

// ---------------- block reduce (256 threads) -------------------------------
__device__ __forceinline__ float block_reduce_sum(float v, float* sh) {
    int t = threadIdx.x;
    sh[t] = v;
    __syncthreads();
    #pragma unroll
    for (int s = 128; s > 0; s >>= 1) {
        if (t < s) sh[t] += sh[t + s];
        __syncthreads();
    }
    float r = sh[0];
    __syncthreads();
    return r;
}

// ---------------- w3 = We @ a3 (len 32), c3 = be . a3 at slot 32 -----------
__global__ void edge_w3_kernel(const float* __restrict__ We, const float* __restrict__ be,
                               const float* __restrict__ a3, float* __restrict__ w3c) {
    int i = threadIdx.x;
    if (i < 33) {
        const float* row = (i < 32) ? (We + i * HD) : be;
        float acc = 0.0f;
        for (int hh = 0; hh < HD; hh++) acc = fmaf(row[hh], a3[hh], acc);
        w3c[i] = acc;
    }
}

// ---------------- s3[e] = edge_feats[e] . w3 + c3 (warp per edge) ----------
__global__ void edge_s3_kernel(const float* __restrict__ ef, const float* __restrict__ w3c,
                               float* __restrict__ s3) {
    int e = blockIdx.x * 8 + (threadIdx.x >> 5);
    int lane = threadIdx.x & 31;
    float v = ef[e * EDGE_IN + lane] * w3c[lane];
    #pragma unroll
    for (int o = 16; o; o >>= 1) v += __shfl_xor_sync(0xffffffffu, v, o);
    if (lane == 0) s3[e] = v + w3c[32];
}

// ---------------- s1[n]=m[n].a1, s2[n]=m[n].a2 (warp per node) -------------
__global__ void node_scores_kernel(const float* __restrict__ m, const float* __restrict__ a,
                                   float* __restrict__ s1, float* __restrict__ s2) {
    int node = blockIdx.x * 8 + (threadIdx.x >> 5);
    int lane = threadIdx.x & 31;
    const float* mr = m + node * HD;
    float acc1 = 0.0f, acc2 = 0.0f;
    #pragma unroll
    for (int i = lane; i < HD; i += 32) {
        float v = mr[i];
        acc1 = fmaf(v, a[i], acc1);
        acc2 = fmaf(v, a[HD + i], acc2);
    }
    #pragma unroll
    for (int o = 16; o; o >>= 1) {
        acc1 += __shfl_xor_sync(0xffffffffu, acc1, o);
        acc2 += __shfl_xor_sync(0xffffffffu, acc2, o);
    }
    if (lane == 0) { s1[node] = acc1; s2[node] = acc2; }
}

// ---------------- GAT aggregate + residual + LN (block=256 per node) -------
__global__ void gat_agg_ln_kernel(const float* __restrict__ m, const int* __restrict__ dst,
                                  const float* __restrict__ s1, const float* __restrict__ s2,
                                  const float* __restrict__ s3,
                                  const float* __restrict__ gamma, const float* __restrict__ beta,
                                  float* __restrict__ h) {
    int n = blockIdx.x, d = threadIdx.x;
    __shared__ float lg[DEG];
    __shared__ int   sdst[DEG];
    __shared__ float sh[256];
    if (d < DEG) {
        int eidx = n * DEG + d;
        int dn = dst[eidx];
        sdst[d] = dn;
        float l = s1[n] + s2[dn] + s3[eidx];
        lg[d] = (l >= 0.0f) ? l : 0.01f * l;
    }
    __syncthreads();
    float mx = -1e30f;
    #pragma unroll
    for (int i = 0; i < DEG; i++) mx = fmaxf(mx, lg[i]);
    float w[DEG]; float den = 0.0f;
    #pragma unroll
    for (int i = 0; i < DEG; i++) { w[i] = expf(lg[i] - mx); den += w[i]; }
    float inv_den = 1.0f / den;
    float agg = 0.0f;
    #pragma unroll
    for (int i = 0; i < DEG; i++)
        agg = fmaf(w[i], m[sdst[i] * HD + d], agg);
    float v = agg * inv_den + h[n * HD + d];
    // LayerNorm eps=1e-5
    float mu = block_reduce_sum(v, sh) * (1.0f / HD);
    float dv = v - mu;
    float var = block_reduce_sum(dv * dv, sh) * (1.0f / HD);
    float inv = rsqrtf(var + 1e-5f);
    h[n * HD + d] = dv * inv * gamma[d] + beta[d];
}

// ---------------- MHA: block per (graph, head), 64 threads -----------------
__global__ void mha_kernel(const float* __restrict__ q, const float* __restrict__ k,
                           const float* __restrict__ v, float* __restrict__ o) {
    int b = blockIdx.x / HEADS, hd = blockIdx.x % HEADS;
    int t = threadIdx.x; // query index 0..63
    __shared__ float ks[NPG][DK];
    __shared__ float vs[NPG][DK];
    int base = (b * NPG) * HD + hd * DK;
    #pragma unroll
    for (int i = 0; i < DK; i++) {
        ks[t][i] = k[base + t * HD + i];
        vs[t][i] = v[base + t * HD + i];
    }
    __syncthreads();
    float qr[DK];
    #pragma unroll
    for (int i = 0; i < DK; i++) qr[i] = q[base + t * HD + i];
    float sc[NPG];
    float mx = -1e30f;
    const float scale = 0.17677669529663687f; // 1/sqrt(32)
    for (int j = 0; j < NPG; j++) {
        float s = 0.0f;
        #pragma unroll
        for (int i = 0; i < DK; i++) s = fmaf(qr[i], ks[j][i], s);
        s *= scale;
        sc[j] = s;
        mx = fmaxf(mx, s);
    }
    float den = 0.0f;
    for (int j = 0; j < NPG; j++) { sc[j] = expf(sc[j] - mx); den += sc[j]; }
    float acc[DK];
    #pragma unroll
    for (int i = 0; i < DK; i++) acc[i] = 0.0f;
    for (int j = 0; j < NPG; j++) {
        float wj = sc[j];
        #pragma unroll
        for (int i = 0; i < DK; i++) acc[i] = fmaf(wj, vs[j][i], acc[i]);
    }
    float inv = 1.0f / den;
    #pragma unroll
    for (int i = 0; i < DK; i++) o[base + t * HD + i] = acc[i] * inv;
}

// ---------------- add + LN (block=256 per row) -----------------------------
__global__ void add_ln_kernel(const float* __restrict__ a, const float* __restrict__ b,
                              const float* __restrict__ gamma, const float* __restrict__ beta,
                              float eps, float* __restrict__ out) {
    int n = blockIdx.x, d = threadIdx.x;
    __shared__ float sh[256];
    float v = a[n * HD + d] + b[n * HD + d];
    float mu = block_reduce_sum(v, sh) * (1.0f / HD);
    float dv = v - mu;
    float var = block_reduce_sum(dv * dv, sh) * (1.0f / HD);
    float inv = rsqrtf(var + eps);
    out[n * HD + d] = dv * inv * gamma[d] + beta[d];
}

// ---------------- gate scalar per node: g = r . w + b2 (warp/node) ---------
__global__ void gate_g_kernel(const float* __restrict__ r, const float* __restrict__ w,
                              const float* __restrict__ b2, float* __restrict__ g) {
    int n = blockIdx.x * 8 + (threadIdx.x >> 5);
    int lane = threadIdx.x & 31;
    float acc = 0.0f;
    #pragma unroll
    for (int i = lane; i < HD; i += 32) acc = fmaf(r[n * HD + i], w[i], acc);
    #pragma unroll
    for (int o = 16; o; o >>= 1) acc += __shfl_xor_sync(0xffffffffu, acc, o);
    if (lane == 0) g[n] = acc + b2[0];
}

// ---------------- readout: softmax over NPG, weighted sum ------------------
__global__ void readout_kernel(const float* __restrict__ x, const float* __restrict__ g,
                               float* __restrict__ out) {
    int b = blockIdx.x, d = threadIdx.x;
    __shared__ float sg[NPG];
    if (d < NPG) sg[d] = g[b * NPG + d];
    __syncthreads();
    float mx = -1e30f;
    #pragma unroll
    for (int i = 0; i < NPG; i++) mx = fmaxf(mx, sg[i]);
    float den = 0.0f;
    #pragma unroll
    for (int i = 0; i < NPG; i++) den += expf(sg[i] - mx);
    float inv = 1.0f / den;
    float acc = 0.0f;
    for (int i = 0; i < NPG; i++) {
        float wi = expf(sg[i] - mx) * inv;
        acc = fmaf(wi, x[(b * NPG + i) * HD + d], acc);
    }
    out[b * HD + d] = acc;
}

// ===========================================================================
extern "C" void kernel_launch(void* const* d_in, const int* in_sizes, int n_in,
                              void* d_out, int out_size) {
    const float* node_feats = (const float*)d_in[0];
    const float* edge_feats = (const float*)d_in[1];
    // const int* src = (const int*)d_in[2];  // src = repeat(arange(N), DEG): implicit
    const int*   dst        = (const int*)d_in[3];
    const float* Wn = (const float*)d_in[4];
    const float* bn = (const float*)d_in[5];
    const float* We = (const float*)d_in[6];
    const float* be = (const float*)d_in[7];
    const float* gat_W   = (const float*)d_in[8];
    const float* gat_a   = (const float*)d_in[9];
    const float* gat_lng = (const float*)d_in[10];
    const float* gat_lnb = (const float*)d_in[11];
    const float* Wq = (const float*)d_in[12];
    const float* Wk = (const float*)d_in[13];
    const float* Wv = (const float*)d_in[14];
    const float* att_lng = (const float*)d_in[15];
    const float* att_lnb = (const float*)d_in[16];
    const float* ff_W1 = (const float*)d_in[17];
    const float* ff_b1 = (const float*)d_in[18];
    const float* ff_W2 = (const float*)d_in[19];
    const float* ff_b2 = (const float*)d_in[20];
    const float* ff_lng = (const float*)d_in[21];
    const float* ff_lnb = (const float*)d_in[22];
    const float* g_W1 = (const float*)d_in[23];
    const float* g_b1 = (const float*)d_in[24];
    const float* g_W2 = (const float*)d_in[25];
    const float* g_b2 = (const float*)d_in[26];
    float* out = (float*)d_out;

    float *h, *m, *s1, *s2, *s3, *w3c, *q, *k, *v, *tmp, *ff, *g;
    cudaGetSymbolAddress((void**)&h,   d_h);
    cudaGetSymbolAddress((void**)&m,   d_m);
    cudaGetSymbolAddress((void**)&s1,  d_s1);
    cudaGetSymbolAddress((void**)&s2,  d_s2);
    cudaGetSymbolAddress((void**)&s3,  d_s3);
    cudaGetSymbolAddress((void**)&w3c, d_w3c);
    cudaGetSymbolAddress((void**)&q,   d_q);
    cudaGetSymbolAddress((void**)&k,   d_k);
    cudaGetSymbolAddress((void**)&v,   d_v);
    cudaGetSymbolAddress((void**)&tmp, d_tmp);
    cudaGetSymbolAddress((void**)&ff,  d_ff);
    cudaGetSymbolAddress((void**)&g,   d_g);

    dim3 tb(32, 32);

    // h = node_feats @ Wn + bn   [NN, HD]
    gemm_kernel<<<dim3(HD/32, NN/32), tb>>>(node_feats, Wn, bn, h, NN, HD, NODE_IN, 0);

    // GAT layers
    for (int l = 0; l < NL; l++) {
        const float* Wl = gat_W + (size_t)l * HD * HD;
        const float* al = gat_a + (size_t)l * 3 * HD;
        // m = h @ Wl
        gemm_kernel<<<dim3(HD/32, NN/32), tb>>>(h, Wl, nullptr, m, NN, HD, HD, 0);
        // s3 via collapsed edge projection
        edge_w3_kernel<<<1, 64>>>(We, be, al + 2 * HD, w3c);
        edge_s3_kernel<<<NE/8, 256>>>(edge_feats, w3c, s3);
        // s1, s2
        node_scores_kernel<<<NN/8, 256>>>(m, al, s1, s2);
        // fused attention-aggregate + residual + LN
        gat_agg_ln_kernel<<<NN, 256>>>(m, dst, s1, s2, s3,
                                       gat_lng + l * HD, gat_lnb + l * HD, h);
    }

    // QKV projections
    gemm_kernel<<<dim3(HD/32, NN/32), tb>>>(h, Wq, nullptr, q, NN, HD, HD, 0);
    gemm_kernel<<<dim3(HD/32, NN/32), tb>>>(h, Wk, nullptr, k, NN, HD, HD, 0);
    gemm_kernel<<<dim3(HD/32, NN/32), tb>>>(h, Wv, nullptr, v, NN, HD, HD, 0);
    // per-graph multi-head attention
    mha_kernel<<<NB * HEADS, NPG>>>(q, k, v, tmp);
    // x = LN(o + x), eps=1e-6
    add_ln_kernel<<<NN, 256>>>(tmp, h, att_lng, att_lnb, 1e-6f, h);

    // FFN
    gemm_kernel<<<dim3(FF/32, NN/32), tb>>>(h, ff_W1, ff_b1, ff, NN, FF, HD, 2);
    gemm_kernel<<<dim3(HD/32, NN/32), tb>>>(ff, ff_W2, ff_b2, tmp, NN, HD, FF, 0);
    add_ln_kernel<<<NN, 256>>>(h, tmp, ff_lng, ff_lnb, 1e-6f, h);

    // Gating readout
    gemm_kernel<<<dim3(HD/32, NN/32), tb>>>(h, g_W1, g_b1, m, NN, HD, HD, 1); // relu
    gate_g_kernel<<<NN/8, 256>>>(m, g_W2, g_b2, g);
    readout_kernel<<<NB, HD>>>(h, g, out);

    (void)in_sizes; (void)n_in; (void)out_size;
}

// round 3
// speedup vs baseline: 2.2443x; 2.2443x over previous
#include <cuda_runtime.h>
#include <cuda_bf16.h>
#include <math.h>
#include <mma.h>
using namespace nvcuda;

// Problem dims
#define NB   256      // graphs (B)
#define NPG  64       // nodes per graph
#define DEG  8
#define NN   (NB*NPG)         // 16384 nodes
#define NE   (NN*DEG)         // 131072 edges
#define NODE_IN 64
#define EDGE_IN 32
#define HD   256      // H
#define NL   4        // GAT layers
#define HEADS 8
#define DK   32       // H/HEADS
#define FF   512      // 2*H

// ---------------- scratch (device globals; no allocation allowed) ----------
__device__ float d_h[NN*HD];       // node state
__device__ float d_m[NN*HD];       // per-layer transformed features / gate relu
__device__ float d_s1[NN];
__device__ float d_s2[NN];
__device__ float d_s3[NL*NE];
__device__ float d_w3c[NL*33];     // per layer: We@a3 (32) + c3 at [32]
__device__ float d_q[NN*HD];
__device__ float d_k[NN*HD];
__device__ float d_v[NN*HD];
__device__ float d_tmp[NN*HD];     // attention out / ff out
__device__ float d_ff[NN*FF];
__device__ float d_g[NN];

// ================= 3xTF32 tensor-core GEMM (fp32-grade accuracy) ==========
// C[M,N] = act(A[M,K] @ B[K,N] + bias). Requires M%128==0, N%128==0, K%16==0.
// act: 0=none, 1=relu, 2=gelu(exact)
#define BM 128
#define BN 128
#define BK 16

__device__ __forceinline__ float tf32_round(float x) {
    return wmma::__float_to_tf32(x);
}

__global__ __launch_bounds__(256) void gemm_tc(
        const float* __restrict__ A, const float* __restrict__ B,
        const float* __restrict__ bias, float* __restrict__ C,
        int M, int N, int K, int act) {
    __shared__ float As[BM][BK + 8];   // 128 x 24
    __shared__ float Bs[BK][BN + 8];   // 16 x 136
    __shared__ float stage[8][16 * 20];

    int tid = threadIdx.x;
    int warpId = tid >> 5;
    int lane = tid & 31;
    int wr = warpId & 1;       // warp row: 2 x 64
    int wc = warpId >> 1;      // warp col: 4 x 32
    int rowBase = blockIdx.y * BM;
    int colBase = blockIdx.x * BN;

    wmma::fragment<wmma::accumulator, 16, 16, 8, float> acc[4][2];
    #pragma unroll
    for (int i = 0; i < 4; i++)
        #pragma unroll
        for (int j = 0; j < 2; j++)
            wmma::fill_fragment(acc[i][j], 0.0f);

    int ar = tid >> 2;              // 0..63
    int ac = (tid & 3) * 4;         // 0,4,8,12
    int br = tid >> 5;              // 0..7
    int bc = (tid & 31) * 4;        // 0..124

    for (int k0 = 0; k0 < K; k0 += BK) {
        *(float4*)&As[ar][ac]      = *(const float4*)&A[(size_t)(rowBase + ar) * K + k0 + ac];
        *(float4*)&As[ar + 64][ac] = *(const float4*)&A[(size_t)(rowBase + ar + 64) * K + k0 + ac];
        *(float4*)&Bs[br][bc]      = *(const float4*)&B[(size_t)(k0 + br) * N + colBase + bc];
        *(float4*)&Bs[br + 8][bc]  = *(const float4*)&B[(size_t)(k0 + br + 8) * N + colBase + bc];
        __syncthreads();

        #pragma unroll
        for (int ks = 0; ks < BK; ks += 8) {
            wmma::fragment<wmma::matrix_a, 16, 16, 8, wmma::precision::tf32, wmma::row_major> fahi[4], falo[4];
            wmma::fragment<wmma::matrix_b, 16, 16, 8, wmma::precision::tf32, wmma::row_major> fbhi[2], fblo[2];
            #pragma unroll
            for (int i = 0; i < 4; i++) {
                wmma::load_matrix_sync(fahi[i], &As[wr * 64 + i * 16][ks], BK + 8);
                #pragma unroll
                for (int t = 0; t < fahi[i].num_elements; t++) {
                    float x = fahi[i].x[t];
                    float hi = tf32_round(x);
                    fahi[i].x[t] = hi;
                    falo[i].x[t] = tf32_round(x - hi);
                }
            }
            #pragma unroll
            for (int j = 0; j < 2; j++) {
                wmma::load_matrix_sync(fbhi[j], &Bs[ks][wc * 32 + j * 16], BN + 8);
                #pragma unroll
                for (int t = 0; t < fbhi[j].num_elements; t++) {
                    float x = fbhi[j].x[t];
                    float hi = tf32_round(x);
                    fbhi[j].x[t] = hi;
                    fblo[j].x[t] = tf32_round(x - hi);
                }
            }
            #pragma unroll
            for (int i = 0; i < 4; i++)
                #pragma unroll
                for (int j = 0; j < 2; j++) {
                    // hi*lo + lo*hi first (small terms), then hi*hi
                    wmma::mma_sync(acc[i][j], fahi[i], fblo[j], acc[i][j]);
                    wmma::mma_sync(acc[i][j], falo[i], fbhi[j], acc[i][j]);
                    wmma::mma_sync(acc[i][j], fahi[i], fbhi[j], acc[i][j]);
                }
        }
        __syncthreads();
    }

    // epilogue: stage each 16x16 frag in smem, apply bias/act, write out
    #pragma unroll
    for (int i = 0; i < 4; i++) {
        #pragma unroll
        for (int j = 0; j < 2; j++) {
            wmma::store_matrix_sync(&stage[warpId][0], acc[i][j], 20, wmma::mem_row_major);
            __syncwarp();
            #pragma unroll
            for (int t = 0; t < 8; t++) {
                int idx = lane + 32 * t;
                int r = idx >> 4, c = idx & 15;
                int grow = rowBase + wr * 64 + i * 16 + r;
                int gcol = colBase + wc * 32 + j * 16 + c;
                float v = stage[warpId][r * 20 + c] + (bias ? bias[gcol] : 0.0f);
                if (act == 1) v = fmaxf(v, 0.0f);
                else if (act == 2) v = 0.5f * v * (1.0f + erff(v * 0.70710678118654752f));
                C[(size_t)grow * N + gcol] = v;
            }
            __syncwarp();
        }
    }
}

// ---------------- block reduce (256 threads) -------------------------------
__device__ __forceinline__ float block_reduce_sum(float v, float* sh) {
    int t = threadIdx.x;
    sh[t] = v;
    __syncthreads();
    #pragma unroll
    for (int s = 128; s > 0; s >>= 1) {
        if (t < s) sh[t] += sh[t + s];
        __syncthreads();
    }
    float r = sh[0];
    __syncthreads();
    return r;
}

// --------- w3[l] = We @ a3_l (len 32), c3_l = be . a3_l, for all layers ----
__global__ void edge_w3_all_kernel(const float* __restrict__ We, const float* __restrict__ be,
                                   const float* __restrict__ gat_a, float* __restrict__ w3c) {
    int i = threadIdx.x;       // 0..131
    int l = i / 33, r = i % 33;
    if (i < NL * 33) {
        const float* a3 = gat_a + l * 3 * HD + 2 * HD;
        const float* row = (r < 32) ? (We + r * HD) : be;
        float acc = 0.0f;
        for (int hh = 0; hh < HD; hh++) acc = fmaf(row[hh], a3[hh], acc);
        w3c[l * 33 + r] = acc;
    }
}

// ------- s3all[l][e] = ef[e] . w3[l] + c3[l] (warp per edge, all layers) ---
__global__ void edge_s3_all_kernel(const float* __restrict__ ef, const float* __restrict__ w3c,
                                   float* __restrict__ s3all) {
    int e = blockIdx.x * 8 + (threadIdx.x >> 5);
    int lane = threadIdx.x & 31;
    float f = ef[e * EDGE_IN + lane];
    #pragma unroll
    for (int l = 0; l < NL; l++) {
        float v = f * w3c[l * 33 + lane];
        #pragma unroll
        for (int o = 16; o; o >>= 1) v += __shfl_xor_sync(0xffffffffu, v, o);
        if (lane == 0) s3all[l * NE + e] = v + w3c[l * 33 + 32];
    }
}

// ---------------- s1[n]=m[n].a1, s2[n]=m[n].a2 (warp per node) -------------
__global__ void node_scores_kernel(const float* __restrict__ m, const float* __restrict__ a,
                                   float* __restrict__ s1, float* __restrict__ s2) {
    int node = blockIdx.x * 8 + (threadIdx.x >> 5);
    int lane = threadIdx.x & 31;
    const float* mr = m + node * HD;
    float acc1 = 0.0f, acc2 = 0.0f;
    #pragma unroll
    for (int i = lane; i < HD; i += 32) {
        float v = mr[i];
        acc1 = fmaf(v, a[i], acc1);
        acc2 = fmaf(v, a[HD + i], acc2);
    }
    #pragma unroll
    for (int o = 16; o; o >>= 1) {
        acc1 += __shfl_xor_sync(0xffffffffu, acc1, o);
        acc2 += __shfl_xor_sync(0xffffffffu, acc2, o);
    }
    if (lane == 0) { s1[node] = acc1; s2[node] = acc2; }
}

// ---------------- GAT aggregate + residual + LN (block=256 per node) -------
__global__ void gat_agg_ln_kernel(const float* __restrict__ m, const int* __restrict__ dst,
                                  const float* __restrict__ s1, const float* __restrict__ s2,
                                  const float* __restrict__ s3,
                                  const float* __restrict__ gamma, const float* __restrict__ beta,
                                  float* __restrict__ h) {
    int n = blockIdx.x, d = threadIdx.x;
    __shared__ float lg[DEG];
    __shared__ int   sdst[DEG];
    __shared__ float sh[256];
    if (d < DEG) {
        int eidx = n * DEG + d;
        int dn = dst[eidx];
        sdst[d] = dn;
        float l = s1[n] + s2[dn] + s3[eidx];
        lg[d] = (l >= 0.0f) ? l : 0.01f * l;
    }
    __syncthreads();
    float mx = -1e30f;
    #pragma unroll
    for (int i = 0; i < DEG; i++) mx = fmaxf(mx, lg[i]);
    float w[DEG]; float den = 0.0f;
    #pragma unroll
    for (int i = 0; i < DEG; i++) { w[i] = expf(lg[i] - mx); den += w[i]; }
    float inv_den = 1.0f / den;
    float agg = 0.0f;
    #pragma unroll
    for (int i = 0; i < DEG; i++)
        agg = fmaf(w[i], m[sdst[i] * HD + d], agg);
    float v = agg * inv_den + h[n * HD + d];
    float mu = block_reduce_sum(v, sh) * (1.0f / HD);
    float dv = v - mu;
    float var = block_reduce_sum(dv * dv, sh) * (1.0f / HD);
    float inv = rsqrtf(var + 1e-5f);
    h[n * HD + d] = dv * inv * gamma[d] + beta[d];
}

// ---------------- MHA: block per (graph, head), 64 threads -----------------
__global__ void mha_kernel(const float* __restrict__ q, const float* __restrict__ k,
                           const float* __restrict__ v, float* __restrict__ o) {
    int b = blockIdx.x / HEADS, hd = blockIdx.x % HEADS;
    int t = threadIdx.x; // query index 0..63
    __shared__ float ks[NPG][DK];
    __shared__ float vs[NPG][DK];
    int base = (b * NPG) * HD + hd * DK;
    #pragma unroll
    for (int i = 0; i < DK; i++) {
        ks[t][i] = k[base + t * HD + i];
        vs[t][i] = v[base + t * HD + i];
    }
    __syncthreads();
    float qr[DK];
    #pragma unroll
    for (int i = 0; i < DK; i++) qr[i] = q[base + t * HD + i];
    float sc[NPG];
    float mx = -1e30f;
    const float scale = 0.17677669529663687f; // 1/sqrt(32)
    for (int j = 0; j < NPG; j++) {
        float s = 0.0f;
        #pragma unroll
        for (int i = 0; i < DK; i++) s = fmaf(qr[i], ks[j][i], s);
        s *= scale;
        sc[j] = s;
        mx = fmaxf(mx, s);
    }
    float den = 0.0f;
    for (int j = 0; j < NPG; j++) { sc[j] = expf(sc[j] - mx); den += sc[j]; }
    float acc[DK];
    #pragma unroll
    for (int i = 0; i < DK; i++) acc[i] = 0.0f;
    for (int j = 0; j < NPG; j++) {
        float wj = sc[j];
        #pragma unroll
        for (int i = 0; i < DK; i++) acc[i] = fmaf(wj, vs[j][i], acc[i]);
    }
    float inv = 1.0f / den;
    #pragma unroll
    for (int i = 0; i < DK; i++) o[base + t * HD + i] = acc[i] * inv;
}

// ---------------- add + LN (block=256 per row) -----------------------------
__global__ void add_ln_kernel(const float* __restrict__ a, const float* __restrict__ b,
                              const float* __restrict__ gamma, const float* __restrict__ beta,
                              float eps, float* __restrict__ out) {
    int n = blockIdx.x, d = threadIdx.x;
    __shared__ float sh[256];
    float v = a[n * HD + d] + b[n * HD + d];
    float mu = block_reduce_sum(v, sh) * (1.0f / HD);
    float dv = v - mu;
    float var = block_reduce_sum(dv * dv, sh) * (1.0f / HD);
    float inv = rsqrtf(var + eps);
    out[n * HD + d] = dv * inv * gamma[d] + beta[d];
}

// ---------------- gate scalar per node: g = r . w + b2 (warp/node) ---------
__global__ void gate_g_kernel(const float* __restrict__ r, const float* __restrict__ w,
                              const float* __restrict__ b2, float* __restrict__ g) {
    int n = blockIdx.x * 8 + (threadIdx.x >> 5);
    int lane = threadIdx.x & 31;
    float acc = 0.0f;
    #pragma unroll
    for (int i = lane; i < HD; i += 32) acc = fmaf(r[n * HD + i], w[i], acc);
    #pragma unroll
    for (int o = 16; o; o >>= 1) acc += __shfl_xor_sync(0xffffffffu, acc, o);
    if (lane == 0) g[n] = acc + b2[0];
}

// ---------------- readout: softmax over NPG, weighted sum ------------------
__global__ void readout_kernel(const float* __restrict__ x, const float* __restrict__ g,
                               float* __restrict__ out) {
    int b = blockIdx.x, d = threadIdx.x;
    __shared__ float sg[NPG];
    if (d < NPG) sg[d] = g[b * NPG + d];
    __syncthreads();
    float mx = -1e30f;
    #pragma unroll
    for (int i = 0; i < NPG; i++) mx = fmaxf(mx, sg[i]);
    float den = 0.0f;
    #pragma unroll
    for (int i = 0; i < NPG; i++) den += expf(sg[i] - mx);
    float inv = 1.0f / den;
    float acc = 0.0f;
    for (int i = 0; i < NPG; i++) {
        float wi = expf(sg[i] - mx) * inv;
        acc = fmaf(wi, x[(b * NPG + i) * HD + d], acc);
    }
    out[b * HD + d] = acc;
}

// ===========================================================================
extern "C" void kernel_launch(void* const* d_in, const int* in_sizes, int n_in,
                              void* d_out, int out_size) {
    const float* node_feats = (const float*)d_in[0];
    const float* edge_feats = (const float*)d_in[1];
    const int*   dst        = (const int*)d_in[3];
    const float* Wn = (const float*)d_in[4];
    const float* bn = (const float*)d_in[5];
    const float* We = (const float*)d_in[6];
    const float* be = (const float*)d_in[7];
    const float* gat_W   = (const float*)d_in[8];
    const float* gat_a   = (const float*)d_in[9];
    const float* gat_lng = (const float*)d_in[10];
    const float* gat_lnb = (const float*)d_in[11];
    const float* Wq = (const float*)d_in[12];
    const float* Wk = (const float*)d_in[13];
    const float* Wv = (const float*)d_in[14];
    const float* att_lng = (const float*)d_in[15];
    const float* att_lnb = (const float*)d_in[16];
    const float* ff_W1 = (const float*)d_in[17];
    const float* ff_b1 = (const float*)d_in[18];
    const float* ff_W2 = (const float*)d_in[19];
    const float* ff_b2 = (const float*)d_in[20];
    const float* ff_lng = (const float*)d_in[21];
    const float* ff_lnb = (const float*)d_in[22];
    const float* g_W1 = (const float*)d_in[23];
    const float* g_b1 = (const float*)d_in[24];
    const float* g_W2 = (const float*)d_in[25];
    const float* g_b2 = (const float*)d_in[26];
    float* out = (float*)d_out;

    float *h, *m, *s1, *s2, *s3, *w3c, *q, *k, *v, *tmp, *ff, *g;
    cudaGetSymbolAddress((void**)&h,   d_h);
    cudaGetSymbolAddress((void**)&m,   d_m);
    cudaGetSymbolAddress((void**)&s1,  d_s1);
    cudaGetSymbolAddress((void**)&s2,  d_s2);
    cudaGetSymbolAddress((void**)&s3,  d_s3);
    cudaGetSymbolAddress((void**)&w3c, d_w3c);
    cudaGetSymbolAddress((void**)&q,   d_q);
    cudaGetSymbolAddress((void**)&k,   d_k);
    cudaGetSymbolAddress((void**)&v,   d_v);
    cudaGetSymbolAddress((void**)&tmp, d_tmp);
    cudaGetSymbolAddress((void**)&ff,  d_ff);
    cudaGetSymbolAddress((void**)&g,   d_g);

    // h = node_feats @ Wn + bn   [NN, HD]
    gemm_tc<<<dim3(HD/BN, NN/BM), 256>>>(node_feats, Wn, bn, h, NN, HD, NODE_IN, 0);

    // all layers' s3 (edge projection collapsed through a3)
    edge_w3_all_kernel<<<1, NL*33>>>(We, be, gat_a, w3c);
    edge_s3_all_kernel<<<NE/8, 256>>>(edge_feats, w3c, s3);

    // GAT layers
    for (int l = 0; l < NL; l++) {
        const float* Wl = gat_W + (size_t)l * HD * HD;
        const float* al = gat_a + (size_t)l * 3 * HD;
        gemm_tc<<<dim3(HD/BN, NN/BM), 256>>>(h, Wl, nullptr, m, NN, HD, HD, 0);
        node_scores_kernel<<<NN/8, 256>>>(m, al, s1, s2);
        gat_agg_ln_kernel<<<NN, 256>>>(m, dst, s1, s2, s3 + (size_t)l * NE,
                                       gat_lng + l * HD, gat_lnb + l * HD, h);
    }

    // QKV projections
    gemm_tc<<<dim3(HD/BN, NN/BM), 256>>>(h, Wq, nullptr, q, NN, HD, HD, 0);
    gemm_tc<<<dim3(HD/BN, NN/BM), 256>>>(h, Wk, nullptr, k, NN, HD, HD, 0);
    gemm_tc<<<dim3(HD/BN, NN/BM), 256>>>(h, Wv, nullptr, v, NN, HD, HD, 0);
    mha_kernel<<<NB * HEADS, NPG>>>(q, k, v, tmp);
    add_ln_kernel<<<NN, 256>>>(tmp, h, att_lng, att_lnb, 1e-6f, h);

    // FFN
    gemm_tc<<<dim3(FF/BN, NN/BM), 256>>>(h, ff_W1, ff_b1, ff, NN, FF, HD, 2);
    gemm_tc<<<dim3(HD/BN, NN/BM), 256>>>(ff, ff_W2, ff_b2, tmp, NN, HD, FF, 0);
    add_ln_kernel<<<NN, 256>>>(h, tmp, ff_lng, ff_lnb, 1e-6f, h);

    // Gating readout
    gemm_tc<<<dim3(HD/BN, NN/BM), 256>>>(h, g_W1, g_b1, m, NN, HD, HD, 1); // relu
    gate_g_kernel<<<NN/8, 256>>>(m, g_W2, g_b2, g);
    readout_kernel<<<NB, HD>>>(h, g, out);

    (void)in_sizes; (void)n_in; (void)out_size;
}

// round 5
// speedup vs baseline: 2.3276x; 1.0371x over previous
#include <cuda_runtime.h>
#include <cuda_bf16.h>
#include <math.h>
#include <mma.h>
using namespace nvcuda;

// Problem dims
#define NB   256
#define NPG  64
#define DEG  8
#define NN   (NB*NPG)         // 16384 nodes
#define NE   (NN*DEG)         // 131072 edges
#define NODE_IN 64
#define EDGE_IN 32
#define HD   256
#define NL   4
#define HEADS 8
#define DK   32
#define FF   512
#define QKV3 (3*HD)           // 768

// ---------------- scratch (device globals) ---------------------------------
__device__ float d_h[NN*HD];
__device__ float d_m[NN*HD];
__device__ float d_s1[NN];
__device__ float d_s2[NN];
__device__ float d_s3[NL*NE];
__device__ float d_w3c[NL*33];
__device__ float d_qkv[NN*QKV3];
__device__ float d_wqkv[HD*QKV3];
__device__ float d_tmp[NN*HD];
__device__ float d_ff[NN*FF];
__device__ float d_g[NN];

// ================= 3xTF32 tensor-core GEMM, double-buffered ================
// C[M,N] = act(A[M,K] @ B[K,N] + bias). M%128==0, N%128==0, K%16==0.
#define BM 128
#define BN 128
#define BK 16
#define A_LD 24                  // 16 + 8 pad
#define B_LD 136                 // 128 + 8 pad
#define A_STAGE (BM*A_LD)        // 3072 floats
#define B_STAGE (BK*B_LD)        // 2176 floats
#define GEMM_SMEM_BYTES ((2*A_STAGE*2 + 2*B_STAGE*2) * 4)   // Ah,Al,Bh,Bl x2 stages

__device__ __forceinline__ float tf32_round(float x) {
    return wmma::__float_to_tf32(x);
}
__device__ __forceinline__ void split4(float4 x, float4& hi, float4& lo) {
    hi.x = tf32_round(x.x); lo.x = tf32_round(x.x - hi.x);
    hi.y = tf32_round(x.y); lo.y = tf32_round(x.y - hi.y);
    hi.z = tf32_round(x.z); lo.z = tf32_round(x.z - hi.z);
    hi.w = tf32_round(x.w); lo.w = tf32_round(x.w - hi.w);
}

__global__ __launch_bounds__(256, 2) void gemm_tc(
        const float* __restrict__ A, const float* __restrict__ B,
        const float* __restrict__ bias, float* __restrict__ C,
        int M, int N, int K, int act) {
    extern __shared__ float smem[];
    float* Ah = smem;                    // [2][A_STAGE]
    float* Al = Ah + 2*A_STAGE;
    float* Bh = Al + 2*A_STAGE;          // [2][B_STAGE]
    float* Bl = Bh + 2*B_STAGE;

    int tid = threadIdx.x;
    int warpId = tid >> 5;
    int lane = tid & 31;
    int wr = warpId & 1;       // 2 x 64 rows
    int wc = warpId >> 1;      // 4 x 32 cols
    int rowBase = blockIdx.y * BM;
    int colBase = blockIdx.x * BN;

    wmma::fragment<wmma::accumulator, 16, 16, 8, float> acc[4][2];
    #pragma unroll
    for (int i = 0; i < 4; i++)
        #pragma unroll
        for (int j = 0; j < 2; j++)
            wmma::fill_fragment(acc[i][j], 0.0f);

    int ar = tid >> 2;              // 0..63
    int ac = (tid & 3) * 4;         // 0,4,8,12
    int br = tid >> 5;              // 0..7
    int bc = (tid & 31) * 4;        // 0..124

    const float* Aptr0 = A + (size_t)(rowBase + ar) * K;
    const float* Aptr1 = A + (size_t)(rowBase + ar + 64) * K;

    // prologue: tile 0
    {
        float4 pa0 = *(const float4*)&Aptr0[ac];
        float4 pa1 = *(const float4*)&Aptr1[ac];
        float4 pb0 = *(const float4*)&B[(size_t)br * N + colBase + bc];
        float4 pb1 = *(const float4*)&B[(size_t)(br + 8) * N + colBase + bc];
        float4 h4, l4;
        split4(pa0, h4, l4);
        *(float4*)&Ah[ar*A_LD + ac] = h4; *(float4*)&Al[ar*A_LD + ac] = l4;
        split4(pa1, h4, l4);
        *(float4*)&Ah[(ar+64)*A_LD + ac] = h4; *(float4*)&Al[(ar+64)*A_LD + ac] = l4;
        split4(pb0, h4, l4);
        *(float4*)&Bh[br*B_LD + bc] = h4; *(float4*)&Bl[br*B_LD + bc] = l4;
        split4(pb1, h4, l4);
        *(float4*)&Bh[(br+8)*B_LD + bc] = h4; *(float4*)&Bl[(br+8)*B_LD + bc] = l4;
    }
    __syncthreads();

    int KT = K / BK;
    for (int kt = 0; kt < KT; kt++) {
        int buf = kt & 1;
        bool pf = (kt + 1 < KT);
        float4 pa0, pa1, pb0, pb1;
        if (pf) {
            int k0 = (kt + 1) * BK;
            pa0 = *(const float4*)&Aptr0[k0 + ac];
            pa1 = *(const float4*)&Aptr1[k0 + ac];
            pb0 = *(const float4*)&B[(size_t)(k0 + br) * N + colBase + bc];
            pb1 = *(const float4*)&B[(size_t)(k0 + br + 8) * N + colBase + bc];
        }

        const float* AhB = Ah + buf * A_STAGE;
        const float* AlB = Al + buf * A_STAGE;
        const float* BhB = Bh + buf * B_STAGE;
        const float* BlB = Bl + buf * B_STAGE;

        #pragma unroll
        for (int ks = 0; ks < BK; ks += 8) {
            wmma::fragment<wmma::matrix_b, 16, 16, 8, wmma::precision::tf32, wmma::row_major> fbh[2], fbl[2];
            #pragma unroll
            for (int j = 0; j < 2; j++) {
                wmma::load_matrix_sync(fbh[j], &BhB[ks*B_LD + wc*32 + j*16], B_LD);
                wmma::load_matrix_sync(fbl[j], &BlB[ks*B_LD + wc*32 + j*16], B_LD);
            }
            #pragma unroll
            for (int i = 0; i < 4; i++) {
                wmma::fragment<wmma::matrix_a, 16, 16, 8, wmma::precision::tf32, wmma::row_major> fah, fal;
                wmma::load_matrix_sync(fah, &AhB[(wr*64 + i*16)*A_LD + ks], A_LD);
                wmma::load_matrix_sync(fal, &AlB[(wr*64 + i*16)*A_LD + ks], A_LD);
                #pragma unroll
                for (int j = 0; j < 2; j++) {
                    wmma::mma_sync(acc[i][j], fah, fbl[j], acc[i][j]);
                    wmma::mma_sync(acc[i][j], fal, fbh[j], acc[i][j]);
                    wmma::mma_sync(acc[i][j], fah, fbh[j], acc[i][j]);
                }
            }
        }

        if (pf) {
            int nbuf = buf ^ 1;
            float* AhN = Ah + nbuf * A_STAGE;
            float* AlN = Al + nbuf * A_STAGE;
            float* BhN = Bh + nbuf * B_STAGE;
            float* BlN = Bl + nbuf * B_STAGE;
            float4 h4, l4;
            split4(pa0, h4, l4);
            *(float4*)&AhN[ar*A_LD + ac] = h4; *(float4*)&AlN[ar*A_LD + ac] = l4;
            split4(pa1, h4, l4);
            *(float4*)&AhN[(ar+64)*A_LD + ac] = h4; *(float4*)&AlN[(ar+64)*A_LD + ac] = l4;
            split4(pb0, h4, l4);
            *(float4*)&BhN[br*B_LD + bc] = h4; *(float4*)&BlN[br*B_LD + bc] = l4;
            split4(pb1, h4, l4);
            *(float4*)&BhN[(br+8)*B_LD + bc] = h4; *(float4*)&BlN[(br+8)*B_LD + bc] = l4;
        }
        __syncthreads();
    }

    // epilogue: reuse smem start as per-warp staging (all compute done)
    float* stage = smem + warpId * 320;   // 16x20 per warp
    #pragma unroll
    for (int i = 0; i < 4; i++) {
        #pragma unroll
        for (int j = 0; j < 2; j++) {
            wmma::store_matrix_sync(stage, acc[i][j], 20, wmma::mem_row_major);
            __syncwarp();
            #pragma unroll
            for (int t = 0; t < 8; t++) {
                int idx = lane + 32 * t;
                int r = idx >> 4, c = idx & 15;
                int grow = rowBase + wr * 64 + i * 16 + r;
                int gcol = colBase + wc * 32 + j * 16 + c;
                float v = stage[r * 20 + c] + (bias ? bias[gcol] : 0.0f);
                if (act == 1) v = fmaxf(v, 0.0f);
                else if (act == 2) v = 0.5f * v * (1.0f + erff(v * 0.70710678118654752f));
                C[(size_t)grow * N + gcol] = v;
            }
            __syncwarp();
        }
    }
}

// ---------------- pack Wq|Wk|Wv into [HD][768] ------------------------------
__global__ void pack_qkv_kernel(const float* __restrict__ Wq, const float* __restrict__ Wk,
                                const float* __restrict__ Wv, float* __restrict__ Wqkv) {
    int idx = blockIdx.x * blockDim.x + threadIdx.x;   // over HD*HD
    if (idx < HD * HD) {
        int r = idx / HD, c = idx % HD;
        Wqkv[r * QKV3 + c]          = Wq[idx];
        Wqkv[r * QKV3 + HD + c]     = Wk[idx];
        Wqkv[r * QKV3 + 2*HD + c]   = Wv[idx];
    }
}

// ---------------- block reduce (256 threads) -------------------------------
__device__ __forceinline__ float block_reduce_sum(float v, float* sh) {
    int t = threadIdx.x;
    sh[t] = v;
    __syncthreads();
    #pragma unroll
    for (int s = 128; s > 0; s >>= 1) {
        if (t < s) sh[t] += sh[t + s];
        __syncthreads();
    }
    float r = sh[0];
    __syncthreads();
    return r;
}

// --------- w3[l] = We @ a3_l (len 32), c3_l = be . a3_l --------------------
__global__ void edge_w3_all_kernel(const float* __restrict__ We, const float* __restrict__ be,
                                   const float* __restrict__ gat_a, float* __restrict__ w3c) {
    int i = threadIdx.x;
    int l = i / 33, r = i % 33;
    if (i < NL * 33) {
        const float* a3 = gat_a + l * 3 * HD + 2 * HD;
        const float* row = (r < 32) ? (We + r * HD) : be;
        float acc = 0.0f;
        for (int hh = 0; hh < HD; hh++) acc = fmaf(row[hh], a3[hh], acc);
        w3c[l * 33 + r] = acc;
    }
}

// ------- s3all[l][e] = ef[e] . w3[l] + c3[l] -------------------------------
__global__ void edge_s3_all_kernel(const float* __restrict__ ef, const float* __restrict__ w3c,
                                   float* __restrict__ s3all) {
    int e = blockIdx.x * 8 + (threadIdx.x >> 5);
    int lane = threadIdx.x & 31;
    float f = ef[e * EDGE_IN + lane];
    #pragma unroll
    for (int l = 0; l < NL; l++) {
        float v = f * w3c[l * 33 + lane];
        #pragma unroll
        for (int o = 16; o; o >>= 1) v += __shfl_xor_sync(0xffffffffu, v, o);
        if (lane == 0) s3all[l * NE + e] = v + w3c[l * 33 + 32];
    }
}

// ---------------- s1/s2 per node -------------------------------------------
__global__ void node_scores_kernel(const float* __restrict__ m, const float* __restrict__ a,
                                   float* __restrict__ s1, float* __restrict__ s2) {
    int node = blockIdx.x * 8 + (threadIdx.x >> 5);
    int lane = threadIdx.x & 31;
    const float* mr = m + node * HD;
    float acc1 = 0.0f, acc2 = 0.0f;
    #pragma unroll
    for (int i = lane; i < HD; i += 32) {
        float v = mr[i];
        acc1 = fmaf(v, a[i], acc1);
        acc2 = fmaf(v, a[HD + i], acc2);
    }
    #pragma unroll
    for (int o = 16; o; o >>= 1) {
        acc1 += __shfl_xor_sync(0xffffffffu, acc1, o);
        acc2 += __shfl_xor_sync(0xffffffffu, acc2, o);
    }
    if (lane == 0) { s1[node] = acc1; s2[node] = acc2; }
}

// ---------------- GAT aggregate + residual + LN ----------------------------
__global__ void gat_agg_ln_kernel(const float* __restrict__ m, const int* __restrict__ dst,
                                  const float* __restrict__ s1, const float* __restrict__ s2,
                                  const float* __restrict__ s3,
                                  const float* __restrict__ gamma, const float* __restrict__ beta,
                                  float* __restrict__ h) {
    int n = blockIdx.x, d = threadIdx.x;
    __shared__ float lg[DEG];
    __shared__ int   sdst[DEG];
    __shared__ float sh[256];
    if (d < DEG) {
        int eidx = n * DEG + d;
        int dn = dst[eidx];
        sdst[d] = dn;
        float l = s1[n] + s2[dn] + s3[eidx];
        lg[d] = (l >= 0.0f) ? l : 0.01f * l;
    }
    __syncthreads();
    float mx = -1e30f;
    #pragma unroll
    for (int i = 0; i < DEG; i++) mx = fmaxf(mx, lg[i]);
    float w[DEG]; float den = 0.0f;
    #pragma unroll
    for (int i = 0; i < DEG; i++) { w[i] = expf(lg[i] - mx); den += w[i]; }
    float inv_den = 1.0f / den;
    float agg = 0.0f;
    #pragma unroll
    for (int i = 0; i < DEG; i++)
        agg = fmaf(w[i], m[sdst[i] * HD + d], agg);
    float v = agg * inv_den + h[n * HD + d];
    float mu = block_reduce_sum(v, sh) * (1.0f / HD);
    float dv = v - mu;
    float var = block_reduce_sum(dv * dv, sh) * (1.0f / HD);
    float inv = rsqrtf(var + 1e-5f);
    h[n * HD + d] = dv * inv * gamma[d] + beta[d];
}

// ---------------- MHA on packed qkv [NN][768] ------------------------------
__global__ void mha_kernel(const float* __restrict__ qkv, float* __restrict__ o) {
    int b = blockIdx.x / HEADS, hd = blockIdx.x % HEADS;
    int t = threadIdx.x; // 0..63
    __shared__ float ks[NPG][DK];
    __shared__ float vs[NPG][DK];
    size_t rowb = (size_t)(b * NPG + t) * QKV3 + hd * DK;
    #pragma unroll
    for (int i = 0; i < DK; i++) {
        ks[t][i] = qkv[rowb + HD + i];
        vs[t][i] = qkv[rowb + 2*HD + i];
    }
    __syncthreads();
    float qr[DK];
    #pragma unroll
    for (int i = 0; i < DK; i++) qr[i] = qkv[rowb + i];
    float sc[NPG];
    float mx = -1e30f;
    const float scale = 0.17677669529663687f;
    for (int j = 0; j < NPG; j++) {
        float s = 0.0f;
        #pragma unroll
        for (int i = 0; i < DK; i++) s = fmaf(qr[i], ks[j][i], s);
        s *= scale;
        sc[j] = s;
        mx = fmaxf(mx, s);
    }
    float den = 0.0f;
    for (int j = 0; j < NPG; j++) { sc[j] = expf(sc[j] - mx); den += sc[j]; }
    float acc[DK];
    #pragma unroll
    for (int i = 0; i < DK; i++) acc[i] = 0.0f;
    for (int j = 0; j < NPG; j++) {
        float wj = sc[j];
        #pragma unroll
        for (int i = 0; i < DK; i++) acc[i] = fmaf(wj, vs[j][i], acc[i]);
    }
    float inv = 1.0f / den;
    size_t obase = (size_t)(b * NPG + t) * HD + hd * DK;
    #pragma unroll
    for (int i = 0; i < DK; i++) o[obase + i] = acc[i] * inv;
}

// ---------------- add + LN --------------------------------------------------
__global__ void add_ln_kernel(const float* __restrict__ a, const float* __restrict__ b,
                              const float* __restrict__ gamma, const float* __restrict__ beta,
                              float eps, float* __restrict__ out) {
    int n = blockIdx.x, d = threadIdx.x;
    __shared__ float sh[256];
    float v = a[n * HD + d] + b[n * HD + d];
    float mu = block_reduce_sum(v, sh) * (1.0f / HD);
    float dv = v - mu;
    float var = block_reduce_sum(dv * dv, sh) * (1.0f / HD);
    float inv = rsqrtf(var + eps);
    out[n * HD + d] = dv * inv * gamma[d] + beta[d];
}

// ---------------- gate scalar per node -------------------------------------
__global__ void gate_g_kernel(const float* __restrict__ r, const float* __restrict__ w,
                              const float* __restrict__ b2, float* __restrict__ g) {
    int n = blockIdx.x * 8 + (threadIdx.x >> 5);
    int lane = threadIdx.x & 31;
    float acc = 0.0f;
    #pragma unroll
    for (int i = lane; i < HD; i += 32) acc = fmaf(r[n * HD + i], w[i], acc);
    #pragma unroll
    for (int o = 16; o; o >>= 1) acc += __shfl_xor_sync(0xffffffffu, acc, o);
    if (lane == 0) g[n] = acc + b2[0];
}

// ---------------- readout ---------------------------------------------------
__global__ void readout_kernel(const float* __restrict__ x, const float* __restrict__ g,
                               float* __restrict__ out) {
    int b = blockIdx.x, d = threadIdx.x;
    __shared__ float sg[NPG];
    if (d < NPG) sg[d] = g[b * NPG + d];
    __syncthreads();
    float mx = -1e30f;
    #pragma unroll
    for (int i = 0; i < NPG; i++) mx = fmaxf(mx, sg[i]);
    float den = 0.0f;
    #pragma unroll
    for (int i = 0; i < NPG; i++) den += expf(sg[i] - mx);
    float inv = 1.0f / den;
    float acc = 0.0f;
    for (int i = 0; i < NPG; i++) {
        float wi = expf(sg[i] - mx) * inv;
        acc = fmaf(wi, x[(b * NPG + i) * HD + d], acc);
    }
    out[b * HD + d] = acc;
}

// ===========================================================================
extern "C" void kernel_launch(void* const* d_in, const int* in_sizes, int n_in,
                              void* d_out, int out_size) {
    const float* node_feats = (const float*)d_in[0];
    const float* edge_feats = (const float*)d_in[1];
    const int*   dst        = (const int*)d_in[3];
    const float* Wn = (const float*)d_in[4];
    const float* bn = (const float*)d_in[5];
    const float* We = (const float*)d_in[6];
    const float* be = (const float*)d_in[7];
    const float* gat_W   = (const float*)d_in[8];
    const float* gat_a   = (const float*)d_in[9];
    const float* gat_lng = (const float*)d_in[10];
    const float* gat_lnb = (const float*)d_in[11];
    const float* Wq = (const float*)d_in[12];
    const float* Wk = (const float*)d_in[13];
    const float* Wv = (const float*)d_in[14];
    const float* att_lng = (const float*)d_in[15];
    const float* att_lnb = (const float*)d_in[16];
    const float* ff_W1 = (const float*)d_in[17];
    const float* ff_b1 = (const float*)d_in[18];
    const float* ff_W2 = (const float*)d_in[19];
    const float* ff_b2 = (const float*)d_in[20];
    const float* ff_lng = (const float*)d_in[21];
    const float* ff_lnb = (const float*)d_in[22];
    const float* g_W1 = (const float*)d_in[23];
    const float* g_b1 = (const float*)d_in[24];
    const float* g_W2 = (const float*)d_in[25];
    const float* g_b2 = (const float*)d_in[26];
    float* out = (float*)d_out;

    float *h, *m, *s1, *s2, *s3, *w3c, *qkv, *wqkv, *tmp, *ff, *g;
    cudaGetSymbolAddress((void**)&h,    d_h);
    cudaGetSymbolAddress((void**)&m,    d_m);
    cudaGetSymbolAddress((void**)&s1,   d_s1);
    cudaGetSymbolAddress((void**)&s2,   d_s2);
    cudaGetSymbolAddress((void**)&s3,   d_s3);
    cudaGetSymbolAddress((void**)&w3c,  d_w3c);
    cudaGetSymbolAddress((void**)&qkv,  d_qkv);
    cudaGetSymbolAddress((void**)&wqkv, d_wqkv);
    cudaGetSymbolAddress((void**)&tmp,  d_tmp);
    cudaGetSymbolAddress((void**)&ff,   d_ff);
    cudaGetSymbolAddress((void**)&g,    d_g);

    static bool attr_done = false;
    if (!attr_done) {
        cudaFuncSetAttribute(gemm_tc, cudaFuncAttributeMaxDynamicSharedMemorySize,
                             GEMM_SMEM_BYTES);
        attr_done = true;
    }

    // h = node_feats @ Wn + bn
    gemm_tc<<<dim3(HD/BN, NN/BM), 256, GEMM_SMEM_BYTES>>>(node_feats, Wn, bn, h, NN, HD, NODE_IN, 0);

    // edge-score precompute (all layers)
    edge_w3_all_kernel<<<1, NL*33>>>(We, be, gat_a, w3c);
    edge_s3_all_kernel<<<NE/8, 256>>>(edge_feats, w3c, s3);
    pack_qkv_kernel<<<(HD*HD + 255)/256, 256>>>(Wq, Wk, Wv, wqkv);

    // GAT layers
    for (int l = 0; l < NL; l++) {
        const float* Wl = gat_W + (size_t)l * HD * HD;
        const float* al = gat_a + (size_t)l * 3 * HD;
        gemm_tc<<<dim3(HD/BN, NN/BM), 256, GEMM_SMEM_BYTES>>>(h, Wl, nullptr, m, NN, HD, HD, 0);
        node_scores_kernel<<<NN/8, 256>>>(m, al, s1, s2);
        gat_agg_ln_kernel<<<NN, 256>>>(m, dst, s1, s2, s3 + (size_t)l * NE,
                                       gat_lng + l * HD, gat_lnb + l * HD, h);
    }

    // fused QKV projection + attention
    gemm_tc<<<dim3(QKV3/BN, NN/BM), 256, GEMM_SMEM_BYTES>>>(h, wqkv, nullptr, qkv, NN, QKV3, HD, 0);
    mha_kernel<<<NB * HEADS, NPG>>>(qkv, tmp);
    add_ln_kernel<<<NN, 256>>>(tmp, h, att_lng, att_lnb, 1e-6f, h);

    // FFN
    gemm_tc<<<dim3(FF/BN, NN/BM), 256, GEMM_SMEM_BYTES>>>(h, ff_W1, ff_b1, ff, NN, FF, HD, 2);
    gemm_tc<<<dim3(HD/BN, NN/BM), 256, GEMM_SMEM_BYTES>>>(ff, ff_W2, ff_b2, tmp, NN, HD, FF, 0);
    add_ln_kernel<<<NN, 256>>>(h, tmp, ff_lng, ff_lnb, 1e-6f, h);

    // Gating readout
    gemm_tc<<<dim3(HD/BN, NN/BM), 256, GEMM_SMEM_BYTES>>>(h, g_W1, g_b1, m, NN, HD, HD, 1);
    gate_g_kernel<<<NN/8, 256>>>(m, g_W2, g_b2, g);
    readout_kernel<<<NB, HD>>>(h, g, out);

    (void)in_sizes; (void)n_in; (void)out_size;
}

// round 6
// speedup vs baseline: 3.9757x; 1.7081x over previous
#include <cuda_runtime.h>
#include <cuda_bf16.h>
#include <math.h>
#include <mma.h>
using namespace nvcuda;

// Problem dims
#define NB   256
#define NPG  64
#define DEG  8
#define NN   (NB*NPG)         // 16384 nodes
#define NE   (NN*DEG)         // 131072 edges
#define NODE_IN 64
#define EDGE_IN 32
#define HD   256
#define NL   4
#define HEADS 8
#define DK   32
#define FF   512
#define QKV3 (3*HD)           // 768

// ---------------- scratch (device globals) ---------------------------------
__device__ float d_h[NN*HD];
__device__ float d_m[NN*HD];
__device__ float d_s1[NN];
__device__ float d_s2[NN];
__device__ float d_s3[NL*NE];
__device__ float d_w3c[NL*33];
__device__ float d_qkv[NN*QKV3];
__device__ float d_wqkv[HD*QKV3];
__device__ float d_tmp[NN*HD];
__device__ float d_ff[NN*FF];
__device__ float d_g[NN];

// ================= 3xBF16 tensor-core GEMM, double-buffered ================
// C[M,N] = act(A[M,K] @ B[K,N] + bias). M%128==0, N%128==0, K%32==0.
// act: 0=none, 1=relu, 2=gelu(exact)
#define BM 128
#define BN 128
#define BK 32
#define A_LD 40                  // 32 + 8 pad (bf16 elems)
#define B_LD 136                 // 128 + 8 pad (bf16 elems)
#define A_STAGE (BM*A_LD)        // 5120 bf16
#define B_STAGE (BK*B_LD)        // 4352 bf16
#define GEMM_SMEM_BYTES ((2*2*A_STAGE + 2*2*B_STAGE) * 2)   // 75776 bytes

// split x into bf16 hi + bf16 lo (lo = bf16(x - hi)), store 4 packed
__device__ __forceinline__ void split_store4(float4 x,
        __nv_bfloat16* __restrict__ hp, __nv_bfloat16* __restrict__ lp) {
    __nv_bfloat16 h0 = __float2bfloat16_rn(x.x);
    __nv_bfloat16 h1 = __float2bfloat16_rn(x.y);
    __nv_bfloat16 h2 = __float2bfloat16_rn(x.z);
    __nv_bfloat16 h3 = __float2bfloat16_rn(x.w);
    __nv_bfloat16 l0 = __float2bfloat16_rn(x.x - __bfloat162float(h0));
    __nv_bfloat16 l1 = __float2bfloat16_rn(x.y - __bfloat162float(h1));
    __nv_bfloat16 l2 = __float2bfloat16_rn(x.z - __bfloat162float(h2));
    __nv_bfloat16 l3 = __float2bfloat16_rn(x.w - __bfloat162float(h3));
    __nv_bfloat162 ph0 = __halves2bfloat162(h0, h1);
    __nv_bfloat162 ph1 = __halves2bfloat162(h2, h3);
    __nv_bfloat162 pl0 = __halves2bfloat162(l0, l1);
    __nv_bfloat162 pl1 = __halves2bfloat162(l2, l3);
    uint2 hv, lv;
    hv.x = *reinterpret_cast<unsigned*>(&ph0);
    hv.y = *reinterpret_cast<unsigned*>(&ph1);
    lv.x = *reinterpret_cast<unsigned*>(&pl0);
    lv.y = *reinterpret_cast<unsigned*>(&pl1);
    *reinterpret_cast<uint2*>(hp) = hv;
    *reinterpret_cast<uint2*>(lp) = lv;
}

__global__ __launch_bounds__(256) void gemm_tc(
        const float* __restrict__ A, const float* __restrict__ B,
        const float* __restrict__ bias, float* __restrict__ C,
        int M, int N, int K, int act) {
    extern __shared__ __align__(16) char smem_raw[];
    __nv_bfloat16* Ah = (__nv_bfloat16*)smem_raw;       // [2][A_STAGE]
    __nv_bfloat16* Al = Ah + 2*A_STAGE;
    __nv_bfloat16* Bh = Al + 2*A_STAGE;                 // [2][B_STAGE]
    __nv_bfloat16* Bl = Bh + 2*B_STAGE;

    int tid = threadIdx.x;
    int warpId = tid >> 5;
    int lane = tid & 31;
    int wr = warpId & 1;       // 2 x 64 rows
    int wc = warpId >> 1;      // 4 x 32 cols
    int rowBase = blockIdx.y * BM;
    int colBase = blockIdx.x * BN;

    wmma::fragment<wmma::accumulator, 16, 16, 16, float> acc[4][2];
    #pragma unroll
    for (int i = 0; i < 4; i++)
        #pragma unroll
        for (int j = 0; j < 2; j++)
            wmma::fill_fragment(acc[i][j], 0.0f);

    // A tile: 128 rows x 32 cols fp32; thread -> (row = t>>3 + 32p, col = (t&7)*4)
    int arow = tid >> 3;
    int acol = (tid & 7) * 4;
    // B tile: 32 rows x 128 cols fp32; thread -> (row = t>>5 + 8p, col = (t&31)*4)
    int brow = tid >> 5;
    int bcol = (tid & 31) * 4;

    float4 pa[4], pb[4];
    // prologue: tile 0
    #pragma unroll
    for (int p = 0; p < 4; p++) {
        pa[p] = *(const float4*)&A[(size_t)(rowBase + arow + 32*p) * K + acol];
        pb[p] = *(const float4*)&B[(size_t)(brow + 8*p) * N + colBase + bcol];
    }
    #pragma unroll
    for (int p = 0; p < 4; p++) {
        int r = arow + 32*p;
        split_store4(pa[p], &Ah[r*A_LD + acol], &Al[r*A_LD + acol]);
        int rb = brow + 8*p;
        split_store4(pb[p], &Bh[rb*B_LD + bcol], &Bl[rb*B_LD + bcol]);
    }
    __syncthreads();

    int KT = K / BK;
    for (int kt = 0; kt < KT; kt++) {
        int buf = kt & 1;
        bool pf = (kt + 1 < KT);
        if (pf) {
            int k0 = (kt + 1) * BK;
            #pragma unroll
            for (int p = 0; p < 4; p++) {
                pa[p] = *(const float4*)&A[(size_t)(rowBase + arow + 32*p) * K + k0 + acol];
                pb[p] = *(const float4*)&B[(size_t)(k0 + brow + 8*p) * N + colBase + bcol];
            }
        }

        const __nv_bfloat16* AhB = Ah + buf * A_STAGE;
        const __nv_bfloat16* AlB = Al + buf * A_STAGE;
        const __nv_bfloat16* BhB = Bh + buf * B_STAGE;
        const __nv_bfloat16* BlB = Bl + buf * B_STAGE;

        #pragma unroll
        for (int ks = 0; ks < BK; ks += 16) {
            wmma::fragment<wmma::matrix_b, 16, 16, 16, __nv_bfloat16, wmma::row_major> fbh[2], fbl[2];
            #pragma unroll
            for (int j = 0; j < 2; j++) {
                wmma::load_matrix_sync(fbh[j], &BhB[ks*B_LD + wc*32 + j*16], B_LD);
                wmma::load_matrix_sync(fbl[j], &BlB[ks*B_LD + wc*32 + j*16], B_LD);
            }
            #pragma unroll
            for (int i = 0; i < 4; i++) {
                wmma::fragment<wmma::matrix_a, 16, 16, 16, __nv_bfloat16, wmma::row_major> fah, fal;
                wmma::load_matrix_sync(fah, &AhB[(wr*64 + i*16)*A_LD + ks], A_LD);
                wmma::load_matrix_sync(fal, &AlB[(wr*64 + i*16)*A_LD + ks], A_LD);
                #pragma unroll
                for (int j = 0; j < 2; j++) {
                    wmma::mma_sync(acc[i][j], fah, fbl[j], acc[i][j]);
                    wmma::mma_sync(acc[i][j], fal, fbh[j], acc[i][j]);
                    wmma::mma_sync(acc[i][j], fah, fbh[j], acc[i][j]);
                }
            }
        }

        if (pf) {
            int nbuf = buf ^ 1;
            __nv_bfloat16* AhN = Ah + nbuf * A_STAGE;
            __nv_bfloat16* AlN = Al + nbuf * A_STAGE;
            __nv_bfloat16* BhN = Bh + nbuf * B_STAGE;
            __nv_bfloat16* BlN = Bl + nbuf * B_STAGE;
            #pragma unroll
            for (int p = 0; p < 4; p++) {
                int r = arow + 32*p;
                split_store4(pa[p], &AhN[r*A_LD + acol], &AlN[r*A_LD + acol]);
                int rb = brow + 8*p;
                split_store4(pb[p], &BhN[rb*B_LD + bcol], &BlN[rb*B_LD + bcol]);
            }
        }
        __syncthreads();
    }

    // epilogue: per-warp smem staging (all compute done; smem reusable)
    float* stage = (float*)smem_raw + warpId * 320;   // 16x20 per warp
    #pragma unroll
    for (int i = 0; i < 4; i++) {
        #pragma unroll
        for (int j = 0; j < 2; j++) {
            wmma::store_matrix_sync(stage, acc[i][j], 20, wmma::mem_row_major);
            __syncwarp();
            #pragma unroll
            for (int t = 0; t < 8; t++) {
                int idx = lane + 32 * t;
                int r = idx >> 4, c = idx & 15;
                int grow = rowBase + wr * 64 + i * 16 + r;
                int gcol = colBase + wc * 32 + j * 16 + c;
                float v = stage[r * 20 + c] + (bias ? bias[gcol] : 0.0f);
                if (act == 1) v = fmaxf(v, 0.0f);
                else if (act == 2) v = 0.5f * v * (1.0f + erff(v * 0.70710678118654752f));
                C[(size_t)grow * N + gcol] = v;
            }
            __syncwarp();
        }
    }
}

// ---------------- pack Wq|Wk|Wv into [HD][768] ------------------------------
__global__ void pack_qkv_kernel(const float* __restrict__ Wq, const float* __restrict__ Wk,
                                const float* __restrict__ Wv, float* __restrict__ Wqkv) {
    int idx = blockIdx.x * blockDim.x + threadIdx.x;
    if (idx < HD * HD) {
        int r = idx / HD, c = idx % HD;
        Wqkv[r * QKV3 + c]          = Wq[idx];
        Wqkv[r * QKV3 + HD + c]     = Wk[idx];
        Wqkv[r * QKV3 + 2*HD + c]   = Wv[idx];
    }
}

// ---------------- block reduce (256 threads) -------------------------------
__device__ __forceinline__ float block_reduce_sum(float v, float* sh) {
    int t = threadIdx.x;
    sh[t] = v;
    __syncthreads();
    #pragma unroll
    for (int s = 128; s > 0; s >>= 1) {
        if (t < s) sh[t] += sh[t + s];
        __syncthreads();
    }
    float r = sh[0];
    __syncthreads();
    return r;
}

// --------- w3[l] = We @ a3_l (len 32), c3_l = be . a3_l --------------------
__global__ void edge_w3_all_kernel(const float* __restrict__ We, const float* __restrict__ be,
                                   const float* __restrict__ gat_a, float* __restrict__ w3c) {
    int i = threadIdx.x;
    int l = i / 33, r = i % 33;
    if (i < NL * 33) {
        const float* a3 = gat_a + l * 3 * HD + 2 * HD;
        const float* row = (r < 32) ? (We + r * HD) : be;
        float acc = 0.0f;
        for (int hh = 0; hh < HD; hh++) acc = fmaf(row[hh], a3[hh], acc);
        w3c[l * 33 + r] = acc;
    }
}

// ------- s3all[l][e] = ef[e] . w3[l] + c3[l] -------------------------------
__global__ void edge_s3_all_kernel(const float* __restrict__ ef, const float* __restrict__ w3c,
                                   float* __restrict__ s3all) {
    int e = blockIdx.x * 8 + (threadIdx.x >> 5);
    int lane = threadIdx.x & 31;
    float f = ef[e * EDGE_IN + lane];
    #pragma unroll
    for (int l = 0; l < NL; l++) {
        float v = f * w3c[l * 33 + lane];
        #pragma unroll
        for (int o = 16; o; o >>= 1) v += __shfl_xor_sync(0xffffffffu, v, o);
        if (lane == 0) s3all[l * NE + e] = v + w3c[l * 33 + 32];
    }
}

// ---------------- s1/s2 per node -------------------------------------------
__global__ void node_scores_kernel(const float* __restrict__ m, const float* __restrict__ a,
                                   float* __restrict__ s1, float* __restrict__ s2) {
    int node = blockIdx.x * 8 + (threadIdx.x >> 5);
    int lane = threadIdx.x & 31;
    const float* mr = m + node * HD;
    float acc1 = 0.0f, acc2 = 0.0f;
    #pragma unroll
    for (int i = lane; i < HD; i += 32) {
        float v = mr[i];
        acc1 = fmaf(v, a[i], acc1);
        acc2 = fmaf(v, a[HD + i], acc2);
    }
    #pragma unroll
    for (int o = 16; o; o >>= 1) {
        acc1 += __shfl_xor_sync(0xffffffffu, acc1, o);
        acc2 += __shfl_xor_sync(0xffffffffu, acc2, o);
    }
    if (lane == 0) { s1[node] = acc1; s2[node] = acc2; }
}

// ---------------- GAT aggregate + residual + LN ----------------------------
__global__ void gat_agg_ln_kernel(const float* __restrict__ m, const int* __restrict__ dst,
                                  const float* __restrict__ s1, const float* __restrict__ s2,
                                  const float* __restrict__ s3,
                                  const float* __restrict__ gamma, const float* __restrict__ beta,
                                  float* __restrict__ h) {
    int n = blockIdx.x, d = threadIdx.x;
    __shared__ float lg[DEG];
    __shared__ int   sdst[DEG];
    __shared__ float sh[256];
    if (d < DEG) {
        int eidx = n * DEG + d;
        int dn = dst[eidx];
        sdst[d] = dn;
        float l = s1[n] + s2[dn] + s3[eidx];
        lg[d] = (l >= 0.0f) ? l : 0.01f * l;
    }
    __syncthreads();
    float mx = -1e30f;
    #pragma unroll
    for (int i = 0; i < DEG; i++) mx = fmaxf(mx, lg[i]);
    float w[DEG]; float den = 0.0f;
    #pragma unroll
    for (int i = 0; i < DEG; i++) { w[i] = expf(lg[i] - mx); den += w[i]; }
    float inv_den = 1.0f / den;
    float agg = 0.0f;
    #pragma unroll
    for (int i = 0; i < DEG; i++)
        agg = fmaf(w[i], m[sdst[i] * HD + d], agg);
    float v = agg * inv_den + h[n * HD + d];
    float mu = block_reduce_sum(v, sh) * (1.0f / HD);
    float dv = v - mu;
    float var = block_reduce_sum(dv * dv, sh) * (1.0f / HD);
    float inv = rsqrtf(var + 1e-5f);
    h[n * HD + d] = dv * inv * gamma[d] + beta[d];
}

// ---------------- MHA on packed qkv [NN][768] ------------------------------
__global__ void mha_kernel(const float* __restrict__ qkv, float* __restrict__ o) {
    int b = blockIdx.x / HEADS, hd = blockIdx.x % HEADS;
    int t = threadIdx.x; // 0..63
    __shared__ float ks[NPG][DK];
    __shared__ float vs[NPG][DK];
    size_t rowb = (size_t)(b * NPG + t) * QKV3 + hd * DK;
    #pragma unroll
    for (int i = 0; i < DK; i++) {
        ks[t][i] = qkv[rowb + HD + i];
        vs[t][i] = qkv[rowb + 2*HD + i];
    }
    __syncthreads();
    float qr[DK];
    #pragma unroll
    for (int i = 0; i < DK; i++) qr[i] = qkv[rowb + i];
    float sc[NPG];
    float mx = -1e30f;
    const float scale = 0.17677669529663687f;
    for (int j = 0; j < NPG; j++) {
        float s = 0.0f;
        #pragma unroll
        for (int i = 0; i < DK; i++) s = fmaf(qr[i], ks[j][i], s);
        s *= scale;
        sc[j] = s;
        mx = fmaxf(mx, s);
    }
    float den = 0.0f;
    for (int j = 0; j < NPG; j++) { sc[j] = expf(sc[j] - mx); den += sc[j]; }
    float acc[DK];
    #pragma unroll
    for (int i = 0; i < DK; i++) acc[i] = 0.0f;
    for (int j = 0; j < NPG; j++) {
        float wj = sc[j];
        #pragma unroll
        for (int i = 0; i < DK; i++) acc[i] = fmaf(wj, vs[j][i], acc[i]);
    }
    float inv = 1.0f / den;
    size_t obase = (size_t)(b * NPG + t) * HD + hd * DK;
    #pragma unroll
    for (int i = 0; i < DK; i++) o[obase + i] = acc[i] * inv;
}

// ---------------- add + LN --------------------------------------------------
__global__ void add_ln_kernel(const float* __restrict__ a, const float* __restrict__ b,
                              const float* __restrict__ gamma, const float* __restrict__ beta,
                              float eps, float* __restrict__ out) {
    int n = blockIdx.x, d = threadIdx.x;
    __shared__ float sh[256];
    float v = a[n * HD + d] + b[n * HD + d];
    float mu = block_reduce_sum(v, sh) * (1.0f / HD);
    float dv = v - mu;
    float var = block_reduce_sum(dv * dv, sh) * (1.0f / HD);
    float inv = rsqrtf(var + eps);
    out[n * HD + d] = dv * inv * gamma[d] + beta[d];
}

// ---------------- gate scalar per node -------------------------------------
__global__ void gate_g_kernel(const float* __restrict__ r, const float* __restrict__ w,
                              const float* __restrict__ b2, float* __restrict__ g) {
    int n = blockIdx.x * 8 + (threadIdx.x >> 5);
    int lane = threadIdx.x & 31;
    float acc = 0.0f;
    #pragma unroll
    for (int i = lane; i < HD; i += 32) acc = fmaf(r[n * HD + i], w[i], acc);
    #pragma unroll
    for (int o = 16; o; o >>= 1) acc += __shfl_xor_sync(0xffffffffu, acc, o);
    if (lane == 0) g[n] = acc + b2[0];
}

// ---------------- readout ---------------------------------------------------
__global__ void readout_kernel(const float* __restrict__ x, const float* __restrict__ g,
                               float* __restrict__ out) {
    int b = blockIdx.x, d = threadIdx.x;
    __shared__ float sg[NPG];
    if (d < NPG) sg[d] = g[b * NPG + d];
    __syncthreads();
    float mx = -1e30f;
    #pragma unroll
    for (int i = 0; i < NPG; i++) mx = fmaxf(mx, sg[i]);
    float den = 0.0f;
    #pragma unroll
    for (int i = 0; i < NPG; i++) den += expf(sg[i] - mx);
    float inv = 1.0f / den;
    float acc = 0.0f;
    for (int i = 0; i < NPG; i++) {
        float wi = expf(sg[i] - mx) * inv;
        acc = fmaf(wi, x[(b * NPG + i) * HD + d], acc);
    }
    out[b * HD + d] = acc;
}

// ===========================================================================
extern "C" void kernel_launch(void* const* d_in, const int* in_sizes, int n_in,
                              void* d_out, int out_size) {
    const float* node_feats = (const float*)d_in[0];
    const float* edge_feats = (const float*)d_in[1];
    const int*   dst        = (const int*)d_in[3];
    const float* Wn = (const float*)d_in[4];
    const float* bn = (const float*)d_in[5];
    const float* We = (const float*)d_in[6];
    const float* be = (const float*)d_in[7];
    const float* gat_W   = (const float*)d_in[8];
    const float* gat_a   = (const float*)d_in[9];
    const float* gat_lng = (const float*)d_in[10];
    const float* gat_lnb = (const float*)d_in[11];
    const float* Wq = (const float*)d_in[12];
    const float* Wk = (const float*)d_in[13];
    const float* Wv = (const float*)d_in[14];
    const float* att_lng = (const float*)d_in[15];
    const float* att_lnb = (const float*)d_in[16];
    const float* ff_W1 = (const float*)d_in[17];
    const float* ff_b1 = (const float*)d_in[18];
    const float* ff_W2 = (const float*)d_in[19];
    const float* ff_b2 = (const float*)d_in[20];
    const float* ff_lng = (const float*)d_in[21];
    const float* ff_lnb = (const float*)d_in[22];
    const float* g_W1 = (const float*)d_in[23];
    const float* g_b1 = (const float*)d_in[24];
    const float* g_W2 = (const float*)d_in[25];
    const float* g_b2 = (const float*)d_in[26];
    float* out = (float*)d_out;

    float *h, *m, *s1, *s2, *s3, *w3c, *qkv, *wqkv, *tmp, *ff, *g;
    cudaGetSymbolAddress((void**)&h,    d_h);
    cudaGetSymbolAddress((void**)&m,    d_m);
    cudaGetSymbolAddress((void**)&s1,   d_s1);
    cudaGetSymbolAddress((void**)&s2,   d_s2);
    cudaGetSymbolAddress((void**)&s3,   d_s3);
    cudaGetSymbolAddress((void**)&w3c,  d_w3c);
    cudaGetSymbolAddress((void**)&qkv,  d_qkv);
    cudaGetSymbolAddress((void**)&wqkv, d_wqkv);
    cudaGetSymbolAddress((void**)&tmp,  d_tmp);
    cudaGetSymbolAddress((void**)&ff,   d_ff);
    cudaGetSymbolAddress((void**)&g,    d_g);

    static bool attr_done = false;
    if (!attr_done) {
        cudaFuncSetAttribute(gemm_tc, cudaFuncAttributeMaxDynamicSharedMemorySize,
                             GEMM_SMEM_BYTES);
        attr_done = true;
    }

    // h = node_feats @ Wn + bn
    gemm_tc<<<dim3(HD/BN, NN/BM), 256, GEMM_SMEM_BYTES>>>(node_feats, Wn, bn, h, NN, HD, NODE_IN, 0);

    // edge-score precompute (all layers) + QKV weight packing
    edge_w3_all_kernel<<<1, NL*33>>>(We, be, gat_a, w3c);
    edge_s3_all_kernel<<<NE/8, 256>>>(edge_feats, w3c, s3);
    pack_qkv_kernel<<<(HD*HD + 255)/256, 256>>>(Wq, Wk, Wv, wqkv);

    // GAT layers
    for (int l = 0; l < NL; l++) {
        const float* Wl = gat_W + (size_t)l * HD * HD;
        const float* al = gat_a + (size_t)l * 3 * HD;
        gemm_tc<<<dim3(HD/BN, NN/BM), 256, GEMM_SMEM_BYTES>>>(h, Wl, nullptr, m, NN, HD, HD, 0);
        node_scores_kernel<<<NN/8, 256>>>(m, al, s1, s2);
        gat_agg_ln_kernel<<<NN, 256>>>(m, dst, s1, s2, s3 + (size_t)l * NE,
                                       gat_lng + l * HD, gat_lnb + l * HD, h);
    }

    // fused QKV projection + attention
    gemm_tc<<<dim3(QKV3/BN, NN/BM), 256, GEMM_SMEM_BYTES>>>(h, wqkv, nullptr, qkv, NN, QKV3, HD, 0);
    mha_kernel<<<NB * HEADS, NPG>>>(qkv, tmp);
    add_ln_kernel<<<NN, 256>>>(tmp, h, att_lng, att_lnb, 1e-6f, h);

    // FFN
    gemm_tc<<<dim3(FF/BN, NN/BM), 256, GEMM_SMEM_BYTES>>>(h, ff_W1, ff_b1, ff, NN, FF, HD, 2);
    gemm_tc<<<dim3(HD/BN, NN/BM), 256, GEMM_SMEM_BYTES>>>(ff, ff_W2, ff_b2, tmp, NN, HD, FF, 0);
    add_ln_kernel<<<NN, 256>>>(h, tmp, ff_lng, ff_lnb, 1e-6f, h);

    // Gating readout
    gemm_tc<<<dim3(HD/BN, NN/BM), 256, GEMM_SMEM_BYTES>>>(h, g_W1, g_b1, m, NN, HD, HD, 1);
    gate_g_kernel<<<NN/8, 256>>>(m, g_W2, g_b2, g);
    readout_kernel<<<NB, HD>>>(h, g, out);

    (void)in_sizes; (void)n_in; (void)out_size;
}

// round 9
// speedup vs baseline: 4.1748x; 1.0501x over previous
#include <cuda_runtime.h>
#include <cuda_bf16.h>
#include <math.h>
#include <mma.h>
using namespace nvcuda;

// Problem dims
#define NB   256
#define NPG  64
#define DEG  8
#define NN   (NB*NPG)         // 16384
#define NE   (NN*DEG)         // 131072
#define NODE_IN 64
#define EDGE_IN 32
#define HD   256
#define NL   4
#define HEADS 8
#define DK   32
#define FF   512
#define QKV3 (3*HD)

// ---------------- scratch (device globals) ---------------------------------
__device__ float d_h[NN*HD];
__device__ float d_m[NN*HD];
__device__ float d_s3[NL*NE];
__device__ float d_w3c[NL*33];
__device__ float d_qkv[NN*QKV3];
__device__ float d_tmp[NN*HD];
__device__ float d_g[NN];
// bf16 hi/lo operand buffers
__device__ __nv_bfloat16 d_nf_h[NN*NODE_IN],  d_nf_l[NN*NODE_IN];
__device__ __nv_bfloat16 d_wn_h[NODE_IN*HD],  d_wn_l[NODE_IN*HD];
__device__ __nv_bfloat16 d_gw_h[NL*HD*HD],    d_gw_l[NL*HD*HD];
__device__ __nv_bfloat16 d_wqkv_h[HD*QKV3],   d_wqkv_l[HD*QKV3];
__device__ __nv_bfloat16 d_ff1_h[HD*FF],      d_ff1_l[HD*FF];
__device__ __nv_bfloat16 d_ff2_h[FF*HD],      d_ff2_l[FF*HD];
__device__ __nv_bfloat16 d_g1_h[HD*HD],       d_g1_l[HD*HD];
__device__ __nv_bfloat16 d_hx_h[NN*HD],       d_hx_l[NN*HD];
__device__ __nv_bfloat16 d_ffx_h[NN*FF],      d_ffx_l[NN*FF];

// ---------------- helpers ---------------------------------------------------
__device__ __forceinline__ void bf16split(float x, __nv_bfloat16& h, __nv_bfloat16& l) {
    h = __float2bfloat16_rn(x);
    l = __float2bfloat16_rn(x - __bfloat162float(h));
}
__device__ __forceinline__ void cp16(void* smem_dst, const void* gmem_src) {
    unsigned s = (unsigned)__cvta_generic_to_shared(smem_dst);
    asm volatile("cp.async.cg.shared.global [%0], [%1], 16;\n" :: "r"(s), "l"(gmem_src));
}
#define CP_COMMIT() asm volatile("cp.async.commit_group;\n" ::: "memory")
#define CP_WAIT(n)  asm volatile("cp.async.wait_group %0;\n" :: "n"(n) : "memory")

// ---------------- generic fp32 -> bf16 hi/lo split --------------------------
__global__ void split_kernel(const float* __restrict__ src,
                             __nv_bfloat16* __restrict__ hi,
                             __nv_bfloat16* __restrict__ lo, int n) {
    int i = blockIdx.x * 256 + threadIdx.x;
    if (i < n) {
        __nv_bfloat16 h, l;
        bf16split(src[i], h, l);
        hi[i] = h; lo[i] = l;
    }
}

// ---------------- pack + split Wq|Wk|Wv into [HD][768] hi/lo ----------------
__global__ void pack_qkv_kernel(const float* __restrict__ Wq, const float* __restrict__ Wk,
                                const float* __restrict__ Wv,
                                __nv_bfloat16* __restrict__ Wh, __nv_bfloat16* __restrict__ Wl) {
    int idx = blockIdx.x * blockDim.x + threadIdx.x;
    if (idx < HD * HD) {
        int r = idx / HD, c = idx % HD;
        __nv_bfloat16 h, l;
        bf16split(Wq[idx], h, l); Wh[r*QKV3 + c] = h;        Wl[r*QKV3 + c] = l;
        bf16split(Wk[idx], h, l); Wh[r*QKV3 + HD + c] = h;   Wl[r*QKV3 + HD + c] = l;
        bf16split(Wv[idx], h, l); Wh[r*QKV3 + 2*HD + c] = h; Wl[r*QKV3 + 2*HD + c] = l;
    }
}

// ================= 3xBF16 GEMM, pre-split operands, cp.async ================
// C = act(A@B + bias); A,B given as bf16 hi/lo. M%128==0, N%128==0, K%32==0.
#define BM 128
#define BN 128
#define BK 32
#define A_LD 40                   // bf16 elems (32 + 8 pad)
#define B_LD 136                  // bf16 elems (128 + 8 pad)
#define A_STAGE (BM*A_LD)         // 5120
#define B_STAGE (BK*B_LD)         // 4352
#define GEMM_SMEM_BYTES ((2*2*A_STAGE + 2*2*B_STAGE)*2)   // 75776

__global__ __launch_bounds__(256) void gemm_bf3(
        const __nv_bfloat16* __restrict__ Ah_g, const __nv_bfloat16* __restrict__ Al_g,
        const __nv_bfloat16* __restrict__ Bh_g, const __nv_bfloat16* __restrict__ Bl_g,
        const float* __restrict__ bias, float* __restrict__ C,
        __nv_bfloat16* __restrict__ Chi, __nv_bfloat16* __restrict__ Clo,
        int M, int N, int K, int act) {
    extern __shared__ __align__(16) char smem_raw[];
    __nv_bfloat16* Ah = (__nv_bfloat16*)smem_raw;   // [2][A_STAGE]
    __nv_bfloat16* Al = Ah + 2*A_STAGE;
    __nv_bfloat16* Bh = Al + 2*A_STAGE;             // [2][B_STAGE]
    __nv_bfloat16* Bl = Bh + 2*B_STAGE;

    int tid = threadIdx.x;
    int warpId = tid >> 5;
    int lane = tid & 31;
    int wr = warpId & 1;
    int wc = warpId >> 1;
    int rowBase = blockIdx.y * BM;
    int colBase = blockIdx.x * BN;

    wmma::fragment<wmma::accumulator, 16, 16, 16, float> acc[4][2];
    #pragma unroll
    for (int i = 0; i < 4; i++)
        #pragma unroll
        for (int j = 0; j < 2; j++)
            wmma::fill_fragment(acc[i][j], 0.0f);

    // per-thread copy coordinates (16B chunks)
    int ac0 = tid;               // chunk ids: tid, tid+256  (A: 512 chunks)
    // A chunk c: row=c>>2, col=(c&3)*8 ; B chunk c: row=c>>4, col=(c&15)*8

    auto issue_tile = [&](int buf, int k0) {
        __nv_bfloat16* AhS = Ah + buf*A_STAGE;
        __nv_bfloat16* AlS = Al + buf*A_STAGE;
        __nv_bfloat16* BhS = Bh + buf*B_STAGE;
        __nv_bfloat16* BlS = Bl + buf*B_STAGE;
        #pragma unroll
        for (int q = 0; q < 2; q++) {
            int c = ac0 + q*256;
            int arow = c >> 2, acol = (c & 3) * 8;
            cp16(&AhS[arow*A_LD + acol], &Ah_g[(size_t)(rowBase + arow)*K + k0 + acol]);
            cp16(&AlS[arow*A_LD + acol], &Al_g[(size_t)(rowBase + arow)*K + k0 + acol]);
            int brow = c >> 4, bcol = (c & 15) * 8;
            cp16(&BhS[brow*B_LD + bcol], &Bh_g[(size_t)(k0 + brow)*N + colBase + bcol]);
            cp16(&BlS[brow*B_LD + bcol], &Bl_g[(size_t)(k0 + brow)*N + colBase + bcol]);
        }
        CP_COMMIT();
    };

    issue_tile(0, 0);

    int KT = K / BK;
    for (int kt = 0; kt < KT; kt++) {
        int buf = kt & 1;
        if (kt + 1 < KT) {
            issue_tile(buf ^ 1, (kt + 1) * BK);
            CP_WAIT(1);
        } else {
            CP_WAIT(0);
        }
        __syncthreads();

        const __nv_bfloat16* AhB = Ah + buf*A_STAGE;
        const __nv_bfloat16* AlB = Al + buf*A_STAGE;
        const __nv_bfloat16* BhB = Bh + buf*B_STAGE;
        const __nv_bfloat16* BlB = Bl + buf*B_STAGE;

        #pragma unroll
        for (int ks = 0; ks < BK; ks += 16) {
            wmma::fragment<wmma::matrix_b, 16, 16, 16, __nv_bfloat16, wmma::row_major> fbh[2], fbl[2];
            #pragma unroll
            for (int j = 0; j < 2; j++) {
                wmma::load_matrix_sync(fbh[j], &BhB[ks*B_LD + wc*32 + j*16], B_LD);
                wmma::load_matrix_sync(fbl[j], &BlB[ks*B_LD + wc*32 + j*16], B_LD);
            }
            #pragma unroll
            for (int i = 0; i < 4; i++) {
                wmma::fragment<wmma::matrix_a, 16, 16, 16, __nv_bfloat16, wmma::row_major> fah, fal;
                wmma::load_matrix_sync(fah, &AhB[(wr*64 + i*16)*A_LD + ks], A_LD);
                wmma::load_matrix_sync(fal, &AlB[(wr*64 + i*16)*A_LD + ks], A_LD);
                #pragma unroll
                for (int j = 0; j < 2; j++) {
                    wmma::mma_sync(acc[i][j], fah, fbl[j], acc[i][j]);
                    wmma::mma_sync(acc[i][j], fal, fbh[j], acc[i][j]);
                    wmma::mma_sync(acc[i][j], fah, fbh[j], acc[i][j]);
                }
            }
        }
        __syncthreads();
    }

    // epilogue
    float* stage = (float*)smem_raw + warpId * 320;   // 16x20 per warp
    #pragma unroll
    for (int i = 0; i < 4; i++) {
        #pragma unroll
        for (int j = 0; j < 2; j++) {
            wmma::store_matrix_sync(stage, acc[i][j], 20, wmma::mem_row_major);
            __syncwarp();
            #pragma unroll
            for (int t = 0; t < 8; t++) {
                int idx = lane + 32*t;
                int r = idx >> 4, c = idx & 15;
                int grow = rowBase + wr*64 + i*16 + r;
                int gcol = colBase + wc*32 + j*16 + c;
                float v = stage[r*20 + c] + (bias ? bias[gcol] : 0.0f);
                if (act == 1) v = fmaxf(v, 0.0f);
                else if (act == 2) v = 0.5f * v * (1.0f + erff(v * 0.70710678118654752f));
                size_t o = (size_t)grow * N + gcol;
                if (C) C[o] = v;
                if (Chi) {
                    __nv_bfloat16 hh, ll;
                    bf16split(v, hh, ll);
                    Chi[o] = hh; Clo[o] = ll;
                }
            }
            __syncwarp();
        }
    }
}

// ---------------- w3/c3 + s3 precompute ------------------------------------
__global__ void edge_w3_all_kernel(const float* __restrict__ We, const float* __restrict__ be,
                                   const float* __restrict__ gat_a, float* __restrict__ w3c) {
    int i = threadIdx.x;
    int l = i / 33, r = i % 33;
    if (i < NL * 33) {
        const float* a3 = gat_a + l * 3 * HD + 2 * HD;
        const float* row = (r < 32) ? (We + r * HD) : be;
        float acc = 0.0f;
        for (int hh = 0; hh < HD; hh++) acc = fmaf(row[hh], a3[hh], acc);
        w3c[l * 33 + r] = acc;
    }
}

__global__ void edge_s3_all_kernel(const float* __restrict__ ef, const float* __restrict__ w3c,
                                   float* __restrict__ s3all) {
    int e = blockIdx.x * 8 + (threadIdx.x >> 5);
    int lane = threadIdx.x & 31;
    float f = ef[e * EDGE_IN + lane];
    #pragma unroll
    for (int l = 0; l < NL; l++) {
        float v = f * w3c[l * 33 + lane];
        #pragma unroll
        for (int o = 16; o; o >>= 1) v += __shfl_xor_sync(0xffffffffu, v, o);
        if (lane == 0) s3all[l * NE + e] = v + w3c[l * 33 + 32];
    }
}

// ============ fused GAT layer tail: block = one graph (64 nodes) ============
// smem: m_g [64][260] f32 | s1[64] | s2[64] | w[64*8] | dstl[64*8] | a[512]
#define M_LD 260
#define GAT_SMEM_FLOATS (64*M_LD + 64 + 64 + 512 + 512 + 512)
#define GAT_SMEM_BYTES (GAT_SMEM_FLOATS*4)

__device__ __forceinline__ float warp_sum(float v) {
    #pragma unroll
    for (int o = 16; o; o >>= 1) v += __shfl_xor_sync(0xffffffffu, v, o);
    return v;
}

__global__ __launch_bounds__(256) void gat_fused_kernel(
        const float* __restrict__ m, const int* __restrict__ dst,
        const float* __restrict__ s3, const float* __restrict__ a12,
        const float* __restrict__ gamma, const float* __restrict__ beta,
        float* __restrict__ h,
        __nv_bfloat16* __restrict__ h_hi, __nv_bfloat16* __restrict__ h_lo) {
    extern __shared__ float sm[];
    float* m_s   = sm;                   // 64*260
    float* s1_s  = m_s + 64*M_LD;        // 64
    float* s2_s  = s1_s + 64;            // 64
    float* w_s   = s2_s + 64;            // 512
    int*   dl_s  = (int*)(w_s + 512);    // 512
    float* a_s   = (float*)(dl_s + 512); // 512

    int g = blockIdx.x;
    int tid = threadIdx.x;
    int warpId = tid >> 5;
    int lane = tid & 31;

    // load a1|a2
    a_s[tid] = a12[tid];
    a_s[tid + 256] = a12[tid + 256];

    // load m graph tile (64 x 256) via float4
    const float4* src = (const float4*)(m + (size_t)g * 64 * HD);
    #pragma unroll
    for (int q = 0; q < 16; q++) {
        int i = tid + q * 256;           // 0..4095
        int n = i >> 6, c = i & 63;
        *(float4*)&m_s[n * M_LD + c * 4] = src[i];
    }
    __syncthreads();

    // s1/s2: warp w handles nodes w*8..w*8+7
    #pragma unroll
    for (int j = 0; j < 8; j++) {
        int n = warpId * 8 + j;
        float a1 = 0.0f, a2 = 0.0f;
        #pragma unroll
        for (int i = 0; i < 8; i++) {
            int dd = lane + 32 * i;
            float v = m_s[n * M_LD + dd];
            a1 = fmaf(v, a_s[dd], a1);
            a2 = fmaf(v, a_s[256 + dd], a2);
        }
        a1 = warp_sum(a1); a2 = warp_sum(a2);
        if (lane == 0) { s1_s[n] = a1; s2_s[n] = a2; }
    }
    __syncthreads();

    // logits + softmax weights: threads 0..63, one node each
    if (tid < 64) {
        int n = tid;
        size_t ebase = ((size_t)g * 64 + n) * DEG;
        float lg[DEG]; int dl[DEG];
        #pragma unroll
        for (int e = 0; e < DEG; e++) {
            int dn = dst[ebase + e];
            dl[e] = dn - g * 64;
            float L = s1_s[n] + s2_s[dl[e]] + s3[ebase + e];
            lg[e] = (L >= 0.0f) ? L : 0.01f * L;
        }
        float mx = -1e30f;
        #pragma unroll
        for (int e = 0; e < DEG; e++) mx = fmaxf(mx, lg[e]);
        float den = 0.0f;
        #pragma unroll
        for (int e = 0; e < DEG; e++) { lg[e] = expf(lg[e] - mx); den += lg[e]; }
        float inv = 1.0f / den;
        #pragma unroll
        for (int e = 0; e < DEG; e++) { w_s[n * DEG + e] = lg[e] * inv; dl_s[n * DEG + e] = dl[e]; }
    }
    __syncthreads();

    // aggregate + residual + LN: warp per node (8 nodes per warp)
    #pragma unroll
    for (int j = 0; j < 8; j++) {
        int n = warpId * 8 + j;
        float wgt[DEG]; int dl[DEG];
        #pragma unroll
        for (int e = 0; e < DEG; e++) { wgt[e] = w_s[n * DEG + e]; dl[e] = dl_s[n * DEG + e]; }
        size_t hbase = ((size_t)g * 64 + n) * HD;
        float vv[8];
        float ssum = 0.0f;
        #pragma unroll
        for (int i = 0; i < 8; i++) {
            int dd = lane + 32 * i;
            float agg = 0.0f;
            #pragma unroll
            for (int e = 0; e < DEG; e++)
                agg = fmaf(wgt[e], m_s[dl[e] * M_LD + dd], agg);
            vv[i] = agg + h[hbase + dd];
            ssum += vv[i];
        }
        float mu = warp_sum(ssum) * (1.0f / HD);
        float vsum = 0.0f;
        #pragma unroll
        for (int i = 0; i < 8; i++) { float dv = vv[i] - mu; vsum += dv * dv; }
        float inv = rsqrtf(warp_sum(vsum) * (1.0f / HD) + 1e-5f);
        #pragma unroll
        for (int i = 0; i < 8; i++) {
            int dd = lane + 32 * i;
            float o = (vv[i] - mu) * inv * gamma[dd] + beta[dd];
            h[hbase + dd] = o;
            __nv_bfloat16 hh, ll;
            bf16split(o, hh, ll);
            h_hi[hbase + dd] = hh; h_lo[hbase + dd] = ll;
        }
    }
}

// ---------------- MHA on packed qkv [NN][768] ------------------------------
__global__ void mha_kernel(const float* __restrict__ qkv, float* __restrict__ o) {
    int b = blockIdx.x / HEADS, hd = blockIdx.x % HEADS;
    int t = threadIdx.x;
    __shared__ float ks[NPG][DK];
    __shared__ float vs[NPG][DK];
    size_t rowb = (size_t)(b * NPG + t) * QKV3 + hd * DK;
    #pragma unroll
    for (int i = 0; i < DK; i++) {
        ks[t][i] = qkv[rowb + HD + i];
        vs[t][i] = qkv[rowb + 2*HD + i];
    }
    __syncthreads();
    float qr[DK];
    #pragma unroll
    for (int i = 0; i < DK; i++) qr[i] = qkv[rowb + i];
    float sc[NPG];
    float mx = -1e30f;
    const float scale = 0.17677669529663687f;
    for (int j = 0; j < NPG; j++) {
        float s = 0.0f;
        #pragma unroll
        for (int i = 0; i < DK; i++) s = fmaf(qr[i], ks[j][i], s);
        s *= scale;
        sc[j] = s;
        mx = fmaxf(mx, s);
    }
    float den = 0.0f;
    for (int j = 0; j < NPG; j++) { sc[j] = expf(sc[j] - mx); den += sc[j]; }
    float acc[DK];
    #pragma unroll
    for (int i = 0; i < DK; i++) acc[i] = 0.0f;
    for (int j = 0; j < NPG; j++) {
        float wj = sc[j];
        #pragma unroll
        for (int i = 0; i < DK; i++) acc[i] = fmaf(wj, vs[j][i], acc[i]);
    }
    float inv = 1.0f / den;
    size_t obase = (size_t)(b * NPG + t) * HD + hd * DK;
    #pragma unroll
    for (int i = 0; i < DK; i++) o[obase + i] = acc[i] * inv;
}

// ---------------- add + LN (+ bf16 hi/lo out) ------------------------------
__device__ __forceinline__ float block_reduce_sum(float v, float* sh) {
    int t = threadIdx.x;
    sh[t] = v;
    __syncthreads();
    #pragma unroll
    for (int s = 128; s > 0; s >>= 1) {
        if (t < s) sh[t] += sh[t + s];
        __syncthreads();
    }
    float r = sh[0];
    __syncthreads();
    return r;
}

__global__ void add_ln_kernel(const float* __restrict__ a, const float* __restrict__ b,
                              const float* __restrict__ gamma, const float* __restrict__ beta,
                              float eps, float* __restrict__ out,
                              __nv_bfloat16* __restrict__ ohi, __nv_bfloat16* __restrict__ olo) {
    int n = blockIdx.x, d = threadIdx.x;
    __shared__ float sh[256];
    float v = a[n * HD + d] + b[n * HD + d];
    float mu = block_reduce_sum(v, sh) * (1.0f / HD);
    float dv = v - mu;
    float var = block_reduce_sum(dv * dv, sh) * (1.0f / HD);
    float inv = rsqrtf(var + eps);
    float o = dv * inv * gamma[d] + beta[d];
    size_t idx = (size_t)n * HD + d;
    out[idx] = o;
    if (ohi) {
        __nv_bfloat16 hh, ll;
        bf16split(o, hh, ll);
        ohi[idx] = hh; olo[idx] = ll;
    }
}

// ---------------- gate scalar + readout ------------------------------------
__global__ void gate_g_kernel(const float* __restrict__ r, const float* __restrict__ w,
                              const float* __restrict__ b2, float* __restrict__ g) {
    int n = blockIdx.x * 8 + (threadIdx.x >> 5);
    int lane = threadIdx.x & 31;
    float acc = 0.0f;
    #pragma unroll
    for (int i = lane; i < HD; i += 32) acc = fmaf(r[n * HD + i], w[i], acc);
    #pragma unroll
    for (int o = 16; o; o >>= 1) acc += __shfl_xor_sync(0xffffffffu, acc, o);
    if (lane == 0) g[n] = acc + b2[0];
}

__global__ void readout_kernel(const float* __restrict__ x, const float* __restrict__ g,
                               float* __restrict__ out) {
    int b = blockIdx.x, d = threadIdx.x;
    __shared__ float sg[NPG];
    if (d < NPG) sg[d] = g[b * NPG + d];
    __syncthreads();
    float mx = -1e30f;
    #pragma unroll
    for (int i = 0; i < NPG; i++) mx = fmaxf(mx, sg[i]);
    float den = 0.0f;
    #pragma unroll
    for (int i = 0; i < NPG; i++) den += expf(sg[i] - mx);
    float inv = 1.0f / den;
    float acc = 0.0f;
    for (int i = 0; i < NPG; i++) {
        float wi = expf(sg[i] - mx) * inv;
        acc = fmaf(wi, x[(b * NPG + i) * HD + d], acc);
    }
    out[b * HD + d] = acc;
}

// ===========================================================================
extern "C" void kernel_launch(void* const* d_in, const int* in_sizes, int n_in,
                              void* d_out, int out_size) {
    const float* node_feats = (const float*)d_in[0];
    const float* edge_feats = (const float*)d_in[1];
    const int*   dst        = (const int*)d_in[3];
    const float* Wn = (const float*)d_in[4];
    const float* bn = (const float*)d_in[5];
    const float* We = (const float*)d_in[6];
    const float* be = (const float*)d_in[7];
    const float* gat_W   = (const float*)d_in[8];
    const float* gat_a   = (const float*)d_in[9];
    const float* gat_lng = (const float*)d_in[10];
    const float* gat_lnb = (const float*)d_in[11];
    const float* Wq = (const float*)d_in[12];
    const float* Wk = (const float*)d_in[13];
    const float* Wv = (const float*)d_in[14];
    const float* att_lng = (const float*)d_in[15];
    const float* att_lnb = (const float*)d_in[16];
    const float* ff_W1 = (const float*)d_in[17];
    const float* ff_b1 = (const float*)d_in[18];
    const float* ff_W2 = (const float*)d_in[19];
    const float* ff_b2 = (const float*)d_in[20];
    const float* ff_lng = (const float*)d_in[21];
    const float* ff_lnb = (const float*)d_in[22];
    const float* g_W1 = (const float*)d_in[23];
    const float* g_b1 = (const float*)d_in[24];
    const float* g_W2 = (const float*)d_in[25];
    const float* g_b2 = (const float*)d_in[26];
    float* out = (float*)d_out;

    float *h, *m, *s3, *w3c, *qkv, *tmp, *g;
    __nv_bfloat16 *nf_h, *nf_l, *wn_h, *wn_l, *gw_h, *gw_l, *wqkv_h, *wqkv_l;
    __nv_bfloat16 *ff1_h, *ff1_l, *ff2_h, *ff2_l, *g1_h, *g1_l;
    __nv_bfloat16 *hx_h, *hx_l, *ffx_h, *ffx_l;
    cudaGetSymbolAddress((void**)&h,    d_h);
    cudaGetSymbolAddress((void**)&m,    d_m);
    cudaGetSymbolAddress((void**)&s3,   d_s3);
    cudaGetSymbolAddress((void**)&w3c,  d_w3c);
    cudaGetSymbolAddress((void**)&qkv,  d_qkv);
    cudaGetSymbolAddress((void**)&tmp,  d_tmp);
    cudaGetSymbolAddress((void**)&g,    d_g);
    cudaGetSymbolAddress((void**)&nf_h, d_nf_h);  cudaGetSymbolAddress((void**)&nf_l, d_nf_l);
    cudaGetSymbolAddress((void**)&wn_h, d_wn_h);  cudaGetSymbolAddress((void**)&wn_l, d_wn_l);
    cudaGetSymbolAddress((void**)&gw_h, d_gw_h);  cudaGetSymbolAddress((void**)&gw_l, d_gw_l);
    cudaGetSymbolAddress((void**)&wqkv_h, d_wqkv_h); cudaGetSymbolAddress((void**)&wqkv_l, d_wqkv_l);
    cudaGetSymbolAddress((void**)&ff1_h, d_ff1_h); cudaGetSymbolAddress((void**)&ff1_l, d_ff1_l);
    cudaGetSymbolAddress((void**)&ff2_h, d_ff2_h); cudaGetSymbolAddress((void**)&ff2_l, d_ff2_l);
    cudaGetSymbolAddress((void**)&g1_h, d_g1_h);  cudaGetSymbolAddress((void**)&g1_l, d_g1_l);
    cudaGetSymbolAddress((void**)&hx_h, d_hx_h);  cudaGetSymbolAddress((void**)&hx_l, d_hx_l);
    cudaGetSymbolAddress((void**)&ffx_h, d_ffx_h); cudaGetSymbolAddress((void**)&ffx_l, d_ffx_l);

    static bool attr_done = false;
    if (!attr_done) {
        cudaFuncSetAttribute(gemm_bf3, cudaFuncAttributeMaxDynamicSharedMemorySize, GEMM_SMEM_BYTES);
        cudaFuncSetAttribute(gat_fused_kernel, cudaFuncAttributeMaxDynamicSharedMemorySize, GAT_SMEM_BYTES);
        attr_done = true;
    }

    // --- operand pre-splits (weights + input) ---
    split_kernel<<<(NN*NODE_IN + 255)/256, 256>>>(node_feats, nf_h, nf_l, NN*NODE_IN);
    split_kernel<<<(NODE_IN*HD + 255)/256, 256>>>(Wn, wn_h, wn_l, NODE_IN*HD);
    split_kernel<<<(NL*HD*HD + 255)/256, 256>>>(gat_W, gw_h, gw_l, NL*HD*HD);
    split_kernel<<<(HD*FF + 255)/256, 256>>>(ff_W1, ff1_h, ff1_l, HD*FF);
    split_kernel<<<(FF*HD + 255)/256, 256>>>(ff_W2, ff2_h, ff2_l, FF*HD);
    split_kernel<<<(HD*HD + 255)/256, 256>>>(g_W1, g1_h, g1_l, HD*HD);
    pack_qkv_kernel<<<(HD*HD + 255)/256, 256>>>(Wq, Wk, Wv, wqkv_h, wqkv_l);
    edge_w3_all_kernel<<<1, NL*33>>>(We, be, gat_a, w3c);
    edge_s3_all_kernel<<<NE/8, 256>>>(edge_feats, w3c, s3);

    // h = node_feats @ Wn + bn  (also emit hi/lo)
    gemm_bf3<<<dim3(HD/BN, NN/BM), 256, GEMM_SMEM_BYTES>>>(
        nf_h, nf_l, wn_h, wn_l, bn, h, hx_h, hx_l, NN, HD, NODE_IN, 0);

    // GAT layers
    for (int l = 0; l < NL; l++) {
        gemm_bf3<<<dim3(HD/BN, NN/BM), 256, GEMM_SMEM_BYTES>>>(
            hx_h, hx_l, gw_h + (size_t)l*HD*HD, gw_l + (size_t)l*HD*HD,
            nullptr, m, nullptr, nullptr, NN, HD, HD, 0);
        gat_fused_kernel<<<NB, 256, GAT_SMEM_BYTES>>>(
            m, dst, s3 + (size_t)l*NE, gat_a + (size_t)l*3*HD,
            gat_lng + l*HD, gat_lnb + l*HD, h, hx_h, hx_l);
    }

    // QKV + attention + LN
    gemm_bf3<<<dim3(QKV3/BN, NN/BM), 256, GEMM_SMEM_BYTES>>>(
        hx_h, hx_l, wqkv_h, wqkv_l, nullptr, qkv, nullptr, nullptr, NN, QKV3, HD, 0);
    mha_kernel<<<NB * HEADS, NPG>>>(qkv, tmp);
    add_ln_kernel<<<NN, 256>>>(tmp, h, att_lng, att_lnb, 1e-6f, h, hx_h, hx_l);

    // FFN
    gemm_bf3<<<dim3(FF/BN, NN/BM), 256, GEMM_SMEM_BYTES>>>(
        hx_h, hx_l, ff1_h, ff1_l, ff_b1, nullptr, ffx_h, ffx_l, NN, FF, HD, 2);
    gemm_bf3<<<dim3(HD/BN, NN/BM), 256, GEMM_SMEM_BYTES>>>(
        ffx_h, ffx_l, ff2_h, ff2_l, ff_b2, tmp, nullptr, nullptr, NN, HD, FF, 0);
    add_ln_kernel<<<NN, 256>>>(h, tmp, ff_lng, ff_lnb, 1e-6f, h, hx_h, hx_l);

    // Gating readout
    gemm_bf3<<<dim3(HD/BN, NN/BM), 256, GEMM_SMEM_BYTES>>>(
        hx_h, hx_l, g1_h, g1_l, g_b1, m, nullptr, nullptr, NN, HD, HD, 1);
    gate_g_kernel<<<NN/8, 256>>>(m, g_W2, g_b2, g);
    readout_kernel<<<NB, HD>>>(h, g, out);

    (void)in_sizes; (void)n_in; (void)out_size;
}